// round 1
// baseline (speedup 1.0000x reference)
#include <cuda_runtime.h>
#include <math.h>

#define D_MODEL 1024
#define SEQ     2048
#define BATCH   4
#define NTOK    (BATCH * SEQ)   /* 8192 */

// ---------------- scratch (device globals; no allocations allowed) ----------
__device__ float g_q[NTOK * D_MODEL];
__device__ float g_k[NTOK * D_MODEL];
__device__ float g_v[NTOK * D_MODEL];
__device__ float g_ctx[NTOK * D_MODEL];
__device__ float g_p[SEQ * D_MODEL];

// ---------------------------------------------------------------------------
// Y[m,n] = sum_k X[m,k] * W[n,k] + bias[n]  (+ P[m mod SEQ, n] if addP)
// X: [M,1024] row-major, W: [1024,1024] row-major (so this is X @ W^T).
// Tile: BM=128, BN=128, BK=32, 256 threads, 8x8 per-thread microtile.
// ---------------------------------------------------------------------------
__global__ __launch_bounds__(256) void gemm_bias_kernel(
    const float* __restrict__ X, const float* __restrict__ W,
    const float* __restrict__ bias, const float* __restrict__ P,
    float* __restrict__ Y, int addP)
{
    __shared__ float As[32][132];
    __shared__ float Bs[32][132];
    const int tid = threadIdx.x;
    const int tx = tid & 15, ty = tid >> 4;
    const int n0 = blockIdx.x << 7;
    const int m0 = blockIdx.y << 7;

    float acc[8][8];
#pragma unroll
    for (int i = 0; i < 8; i++)
#pragma unroll
        for (int j = 0; j < 8; j++) acc[i][j] = 0.f;

    for (int k0 = 0; k0 < D_MODEL; k0 += 32) {
#pragma unroll
        for (int i = 0; i < 4; i++) {
            int idx = tid + (i << 8);
            int r = idx >> 3, c = (idx & 7) << 2;
            float4 a = *(const float4*)(X + (size_t)(m0 + r) * D_MODEL + k0 + c);
            As[c + 0][r] = a.x; As[c + 1][r] = a.y;
            As[c + 2][r] = a.z; As[c + 3][r] = a.w;
            float4 b = *(const float4*)(W + (size_t)(n0 + r) * D_MODEL + k0 + c);
            Bs[c + 0][r] = b.x; Bs[c + 1][r] = b.y;
            Bs[c + 2][r] = b.z; Bs[c + 3][r] = b.w;
        }
        __syncthreads();
#pragma unroll
        for (int kk = 0; kk < 32; kk++) {
            float a[8], b[8];
            *(float4*)&a[0] = *(const float4*)&As[kk][ty * 8];
            *(float4*)&a[4] = *(const float4*)&As[kk][ty * 8 + 4];
            *(float4*)&b[0] = *(const float4*)&Bs[kk][tx * 8];
            *(float4*)&b[4] = *(const float4*)&Bs[kk][tx * 8 + 4];
#pragma unroll
            for (int i = 0; i < 8; i++)
#pragma unroll
                for (int j = 0; j < 8; j++)
                    acc[i][j] = fmaf(a[i], b[j], acc[i][j]);
        }
        __syncthreads();
    }

#pragma unroll
    for (int i = 0; i < 8; i++) {
        int m = m0 + ty * 8 + i;
#pragma unroll
        for (int j4 = 0; j4 < 2; j4++) {
            int n = n0 + tx * 8 + j4 * 4;
            float4 r;
            r.x = acc[i][j4 * 4 + 0] + bias[n + 0];
            r.y = acc[i][j4 * 4 + 1] + bias[n + 1];
            r.z = acc[i][j4 * 4 + 2] + bias[n + 2];
            r.w = acc[i][j4 * 4 + 3] + bias[n + 3];
            if (addP) {
                const float* pp = P + (size_t)(m & (SEQ - 1)) * D_MODEL + n;
                r.x += pp[0]; r.y += pp[1]; r.z += pp[2]; r.w += pp[3];
            }
            *(float4*)(Y + (size_t)m * D_MODEL + n) = r;
        }
    }
}

// ---------------------------------------------------------------------------
// Flash attention, fp32, causal. One block = 32 queries of one (b,h).
// 128 threads: tx (0..15) covers 64 j/d columns x4, ty (0..7) covers 32 q x4.
// smem: Qs/Ps [32][64], Kt/Vs [64][64] = 48KB static.
// Q, P row-swizzle (col ^ ((row&4)<<2)) and K kk-group swizzle give
// conflict-free LDS.128 in the inner loops.
// ---------------------------------------------------------------------------
__global__ __launch_bounds__(128) void flash_attn_kernel(
    const float* __restrict__ Q, const float* __restrict__ K,
    const float* __restrict__ V, float* __restrict__ O)
{
    __shared__ float Qs[32][64];
    __shared__ float Kt[64][64];   // [kk][j], col = j ^ (kk & ~3)
    __shared__ float Vs[64][64];   // [j][d]
    __shared__ float Ps[32][64];

    const int tid = threadIdx.x;
    const int tx = tid & 15, ty = tid >> 4;
    const int qt = blockIdx.x;          // 0..63
    const int bh = blockIdx.y;          // 0..63
    const int b = bh >> 4, h = bh & 15;
    const int q0 = qt << 5;
    const size_t base = ((size_t)b * SEQ) * D_MODEL + h * 64;

    // load Q tile (rows q0..q0+31, head slice), swizzled
#pragma unroll
    for (int i = 0; i < 4; i++) {
        int idx = tid + (i << 7);
        int r = idx >> 4, c = (idx & 15) << 2;
        float4 t = *(const float4*)(Q + base + (size_t)(q0 + r) * D_MODEL + c);
        *(float4*)&Qs[r][c ^ ((r & 4) << 2)] = t;
    }

    float acc[4][4];
    float mi[4], li[4];
#pragma unroll
    for (int i = 0; i < 4; i++) {
        mi[i] = -1e30f; li[i] = 0.f;
#pragma unroll
        for (int j = 0; j < 4; j++) acc[i][j] = 0.f;
    }

    const int ntiles = (q0 + 95) >> 6;
    for (int t = 0; t < ntiles; t++) {
        const int j0 = t << 6;
        __syncthreads();  // Kt/Vs free (prev PV done); Qs load visible on t==0
#pragma unroll
        for (int i = 0; i < 8; i++) {
            int idx = tid + (i << 7);
            int r = idx >> 4, c = (idx & 15) << 2;
            float4 kf = *(const float4*)(K + base + (size_t)(j0 + r) * D_MODEL + c);
            int jc = r ^ c;               // c == (kk & ~3) for kk in c..c+3
            Kt[c + 0][jc] = kf.x;
            Kt[c + 1][jc] = kf.y;
            Kt[c + 2][jc] = kf.z;
            Kt[c + 3][jc] = kf.w;
            float4 vf = *(const float4*)(V + base + (size_t)(j0 + r) * D_MODEL + c);
            *(float4*)&Vs[r][c] = vf;
        }
        __syncthreads();

        // scores S = Q K^T
        float s[4][4];
#pragma unroll
        for (int i = 0; i < 4; i++)
#pragma unroll
            for (int j = 0; j < 4; j++) s[i][j] = 0.f;

#pragma unroll
        for (int k4 = 0; k4 < 16; k4++) {
            const int kc = k4 << 2;
            float4 qf[4], kf[4];
#pragma unroll
            for (int i = 0; i < 4; i++) {
                int row = ty * 4 + i;
                qf[i] = *(const float4*)&Qs[row][kc ^ ((row & 4) << 2)];
            }
#pragma unroll
            for (int u = 0; u < 4; u++)
                kf[u] = *(const float4*)&Kt[kc + u][(tx << 2) ^ kc];
#pragma unroll
            for (int i = 0; i < 4; i++) {
                const float* qv = (const float*)&qf[i];
#pragma unroll
                for (int u = 0; u < 4; u++) {
                    float qa = qv[u];
                    s[i][0] = fmaf(qa, kf[u].x, s[i][0]);
                    s[i][1] = fmaf(qa, kf[u].y, s[i][1]);
                    s[i][2] = fmaf(qa, kf[u].z, s[i][2]);
                    s[i][3] = fmaf(qa, kf[u].w, s[i][3]);
                }
            }
        }

        // scale + causal mask + online softmax (row reduce over 16 tx lanes)
        const bool maskTile = (t == ntiles - 1);
#pragma unroll
        for (int i = 0; i < 4; i++) {
            int row = ty * 4 + i;
            int qg = q0 + row;
#pragma unroll
            for (int j = 0; j < 4; j++) {
                float sv = s[i][j] * 0.125f;
                if (maskTile && (j0 + (tx << 2) + j > qg)) sv = -1e30f;
                s[i][j] = sv;
            }
            float rmax = fmaxf(fmaxf(s[i][0], s[i][1]), fmaxf(s[i][2], s[i][3]));
#pragma unroll
            for (int off = 8; off > 0; off >>= 1)
                rmax = fmaxf(rmax, __shfl_xor_sync(0xffffffffu, rmax, off));
            float mnew = fmaxf(mi[i], rmax);
            float corr = __expf(mi[i] - mnew);
            mi[i] = mnew;
            float rsum = 0.f;
#pragma unroll
            for (int j = 0; j < 4; j++) {
                float p = __expf(s[i][j] - mnew);
                s[i][j] = p;
                rsum += p;
            }
#pragma unroll
            for (int off = 8; off > 0; off >>= 1)
                rsum += __shfl_xor_sync(0xffffffffu, rsum, off);
            li[i] = li[i] * corr + rsum;
#pragma unroll
            for (int j = 0; j < 4; j++) acc[i][j] *= corr;
            *(float4*)&Ps[row][(tx << 2) ^ ((row & 4) << 2)] = *(float4*)&s[i][0];
        }
        __syncthreads();

        // O += P V
#pragma unroll
        for (int j4 = 0; j4 < 16; j4++) {
            const int jc = j4 << 2;
            float4 pf[4], vf[4];
#pragma unroll
            for (int i = 0; i < 4; i++) {
                int row = ty * 4 + i;
                pf[i] = *(const float4*)&Ps[row][jc ^ ((row & 4) << 2)];
            }
#pragma unroll
            for (int u = 0; u < 4; u++)
                vf[u] = *(const float4*)&Vs[jc + u][tx << 2];
#pragma unroll
            for (int i = 0; i < 4; i++) {
                const float* pv = (const float*)&pf[i];
#pragma unroll
                for (int u = 0; u < 4; u++) {
                    float pa = pv[u];
                    acc[i][0] = fmaf(pa, vf[u].x, acc[i][0]);
                    acc[i][1] = fmaf(pa, vf[u].y, acc[i][1]);
                    acc[i][2] = fmaf(pa, vf[u].z, acc[i][2]);
                    acc[i][3] = fmaf(pa, vf[u].w, acc[i][3]);
                }
            }
        }
    }

    // epilogue: normalize and store context (ctx[b, s, h*64 + d])
#pragma unroll
    for (int i = 0; i < 4; i++) {
        float inv = 1.f / li[i];
        float4 r;
        r.x = acc[i][0] * inv; r.y = acc[i][1] * inv;
        r.z = acc[i][2] * inv; r.w = acc[i][3] * inv;
        *(float4*)(O + base + (size_t)(q0 + ty * 4 + i) * D_MODEL + (tx << 2)) = r;
    }
}

// ---------------------------------------------------------------------------
extern "C" void kernel_launch(void* const* d_in, const int* in_sizes, int n_in,
                              void* d_out, int out_size)
{
    const float* x   = (const float*)d_in[0];
    const float* pos = (const float*)d_in[1];
    const float* Wq  = (const float*)d_in[2];
    const float* bq  = (const float*)d_in[3];
    const float* Wk  = (const float*)d_in[4];
    const float* bk  = (const float*)d_in[5];
    const float* Wv  = (const float*)d_in[6];
    const float* bv  = (const float*)d_in[7];
    const float* Wp  = (const float*)d_in[8];
    const float* bp  = (const float*)d_in[9];
    const float* Wo  = (const float*)d_in[10];
    const float* bo  = (const float*)d_in[11];
    float* out = (float*)d_out;

    float *q, *k, *v, *ctx, *p;
    cudaGetSymbolAddress((void**)&q,   g_q);
    cudaGetSymbolAddress((void**)&k,   g_k);
    cudaGetSymbolAddress((void**)&v,   g_v);
    cudaGetSymbolAddress((void**)&ctx, g_ctx);
    cudaGetSymbolAddress((void**)&p,   g_p);

    dim3 blk(256);
    dim3 gP(D_MODEL / 128, SEQ / 128);
    dim3 gX(D_MODEL / 128, NTOK / 128);

    // p = pos_emb @ Wp^T + bp
    gemm_bias_kernel<<<gP, blk>>>(pos, Wp, bp, nullptr, p, 0);
    // q = x @ Wq^T + bq + p[s]
    gemm_bias_kernel<<<gX, blk>>>(x, Wq, bq, p, q, 1);
    // k, v
    gemm_bias_kernel<<<gX, blk>>>(x, Wk, bk, nullptr, k, 0);
    gemm_bias_kernel<<<gX, blk>>>(x, Wv, bv, nullptr, v, 0);
    // causal attention -> ctx
    flash_attn_kernel<<<dim3(SEQ / 32, BATCH * 16), 128>>>(q, k, v, ctx);
    // out = ctx @ Wo^T + bo
    gemm_bias_kernel<<<gX, blk>>>(ctx, Wo, bo, nullptr, out, 0);
}

// round 3
// speedup vs baseline: 1.9056x; 1.9056x over previous
#include <cuda_runtime.h>
#include <cstdint>
#include <math.h>

#define D_MODEL 1024
#define SEQ     2048
#define BATCH   4
#define NTOK    (BATCH * SEQ)   /* 8192 */

// ---------------- scratch (device globals; no allocations allowed) ----------
__device__ float g_q[NTOK * D_MODEL];
__device__ float g_k[NTOK * D_MODEL];
__device__ float g_v[NTOK * D_MODEL];
__device__ float g_ctx[NTOK * D_MODEL];
__device__ float g_p[SEQ * D_MODEL];

// ============================ helpers =======================================
#define CP_ASYNC16(dst, src) \
    asm volatile("cp.async.cg.shared.global [%0], [%1], 16;" \
                 :: "r"(dst), "l"(src) : "memory")
#define CP_COMMIT() asm volatile("cp.async.commit_group;" ::: "memory")
#define CP_WAIT(n)  asm volatile("cp.async.wait_group %0;" :: "n"(n) : "memory")

#define SW128(off) ((off) ^ (((off) >> 3) & 0x70))

__device__ __forceinline__ uint32_t smem_u32(const void* p) {
    uint32_t a;
    asm("{ .reg .u64 t; cvta.to.shared.u64 t, %1; cvt.u32.u64 %0, t; }"
        : "=r"(a) : "l"(p));
    return a;
}

__device__ __forceinline__ uint32_t f2tf32(float f) {
    uint32_t r;
    asm("cvt.rna.tf32.f32 %0, %1;" : "=r"(r) : "f"(f));
    return r;
}

#define MMA_TF32(c0, c1, c2, c3, a0, a1, a2, a3, b0, b1) \
    asm volatile( \
        "mma.sync.aligned.m16n8k8.row.col.f32.tf32.tf32.f32 " \
        "{%0,%1,%2,%3}, {%4,%5,%6,%7}, {%8,%9}, {%0,%1,%2,%3};" \
        : "+f"(c0), "+f"(c1), "+f"(c2), "+f"(c3) \
        : "r"(a0), "r"(a1), "r"(a2), "r"(a3), "r"(b0), "r"(b1))

// ============================ mma.sync tf32 GEMM ============================
// Y[m,n] = sum_k X[m,k]*W[n,k] + bias[n] (+ P[m mod SEQ, n] if addP)
// Tile 128x128x32, 8 warps (2 M x 4 N), warp tile 64x32 (4 mfrag x 4 nfrag),
// 4-stage cp.async pipeline, SW128-swizzled smem, fragments via scalar LDS.
#define BM 128
#define BN 128
#define BK 32
#define GSTAGES 4
#define NCHUNK (D_MODEL / BK)      /* 32 */
#define TILE_B (BM * BK * 4)       /* 16384 bytes, same for A and B */
#define STG_B  (2 * TILE_B)        /* 32768 per stage */
#define SM_TOTAL (GSTAGES * STG_B) /* 131072 */

__device__ __forceinline__ float lds_sw(const char* base, int r, int c) {
    return *(const float*)(base + SW128(r * 128 + c * 4));
}

__device__ __forceinline__ void gemm_load_chunk(
    const float* __restrict__ X, const float* __restrict__ W,
    uint32_t sbase, int stage, int m0, int n0, int kof, int tid)
{
    const uint32_t abase = sbase + stage * STG_B;
    const uint32_t bbase = abase + TILE_B;
#pragma unroll
    for (int i = 0; i < 4; i++) {
        int seg = tid + (i << 8);
        int row = seg >> 3, c16 = seg & 7;
        uint32_t off = row * 128 + c16 * 16;
        CP_ASYNC16(abase + SW128(off),
                   X + (size_t)(m0 + row) * D_MODEL + kof + c16 * 4);
    }
#pragma unroll
    for (int i = 0; i < 4; i++) {
        int seg = tid + (i << 8);
        int row = seg >> 3, c16 = seg & 7;
        uint32_t off = row * 128 + c16 * 16;
        CP_ASYNC16(bbase + SW128(off),
                   W + (size_t)(n0 + row) * D_MODEL + kof + c16 * 4);
    }
}

__global__ __launch_bounds__(256, 1) void gemm_mma_kernel(
    const float* __restrict__ X, const float* __restrict__ W,
    const float* __restrict__ bias, const float* __restrict__ P,
    float* __restrict__ Y, int addP)
{
    extern __shared__ char smem[];
    const uint32_t sb = smem_u32(smem);
    const int tid = threadIdx.x;
    const int lane = tid & 31, wid = tid >> 5;
    const int wm = wid >> 2;          // 0..1
    const int wn = wid & 3;           // 0..3
    const int n0 = blockIdx.x * BN;
    const int m0 = blockIdx.y * BM;

    float acc[4][4][4];
#pragma unroll
    for (int f = 0; f < 4; f++)
#pragma unroll
        for (int g = 0; g < 4; g++)
#pragma unroll
            for (int e = 0; e < 4; e++) acc[f][g][e] = 0.f;

    // prologue: stages 0..2
#pragma unroll
    for (int c = 0; c < GSTAGES - 1; c++) {
        gemm_load_chunk(X, W, sb, c, m0, n0, c * BK, tid);
        CP_COMMIT();
    }

    const int lq = lane >> 2;   // 0..7
    const int lr = lane & 3;    // 0..3

    for (int m = 0; m < NCHUNK; m++) {
        CP_WAIT(GSTAGES - 2);
        __syncthreads();

        const int pc = m + GSTAGES - 1;
        if (pc < NCHUNK)
            gemm_load_chunk(X, W, sb, pc & (GSTAGES - 1), m0, n0, pc * BK, tid);
        CP_COMMIT();

        const char* as = smem + (m & (GSTAGES - 1)) * STG_B;
        const char* bs = as + TILE_B;
#pragma unroll
        for (int ks = 0; ks < 4; ks++) {
            const int kc = ks * 8 + lr;
            uint32_t A[4][4];
#pragma unroll
            for (int f = 0; f < 4; f++) {
                const int r = wm * 64 + f * 16 + lq;
                A[f][0] = f2tf32(lds_sw(as, r,     kc));
                A[f][1] = f2tf32(lds_sw(as, r + 8, kc));
                A[f][2] = f2tf32(lds_sw(as, r,     kc + 4));
                A[f][3] = f2tf32(lds_sw(as, r + 8, kc + 4));
            }
            uint32_t B[4][2];
#pragma unroll
            for (int g = 0; g < 4; g++) {
                const int n = wn * 32 + g * 8 + lq;
                B[g][0] = f2tf32(lds_sw(bs, n, kc));
                B[g][1] = f2tf32(lds_sw(bs, n, kc + 4));
            }
#pragma unroll
            for (int f = 0; f < 4; f++)
#pragma unroll
                for (int g = 0; g < 4; g++)
                    MMA_TF32(acc[f][g][0], acc[f][g][1], acc[f][g][2], acc[f][g][3],
                             A[f][0], A[f][1], A[f][2], A[f][3],
                             B[g][0], B[g][1]);
        }
    }

    // epilogue: C frag rows (lq, lq+8), cols 2*lr, 2*lr+1 -> float2 stores
#pragma unroll
    for (int f = 0; f < 4; f++) {
        const int r0 = m0 + wm * 64 + f * 16 + lq;
#pragma unroll
        for (int g = 0; g < 4; g++) {
            const int nc = n0 + wn * 32 + g * 8 + 2 * lr;
            float2 bz = *(const float2*)(bias + nc);
            float2 v0, v1;
            v0.x = acc[f][g][0] + bz.x; v0.y = acc[f][g][1] + bz.y;
            v1.x = acc[f][g][2] + bz.x; v1.y = acc[f][g][3] + bz.y;
            if (addP) {
                float2 p0 = *(const float2*)(P + (size_t)(r0 & (SEQ - 1)) * D_MODEL + nc);
                float2 p1 = *(const float2*)(P + (size_t)((r0 + 8) & (SEQ - 1)) * D_MODEL + nc);
                v0.x += p0.x; v0.y += p0.y;
                v1.x += p1.x; v1.y += p1.y;
            }
            *(float2*)(Y + (size_t)r0 * D_MODEL + nc) = v0;
            *(float2*)(Y + (size_t)(r0 + 8) * D_MODEL + nc) = v1;
        }
    }
}

// ---------------------------------------------------------------------------
// Flash attention, fp32, causal (unchanged from R1 passing version).
// ---------------------------------------------------------------------------
__global__ __launch_bounds__(128) void flash_attn_kernel(
    const float* __restrict__ Q, const float* __restrict__ K,
    const float* __restrict__ V, float* __restrict__ O)
{
    __shared__ float Qs[32][64];
    __shared__ float Kt[64][64];
    __shared__ float Vs[64][64];
    __shared__ float Ps[32][64];

    const int tid = threadIdx.x;
    const int tx = tid & 15, ty = tid >> 4;
    const int qt = blockIdx.x;
    const int bh = blockIdx.y;
    const int b = bh >> 4, h = bh & 15;
    const int q0 = qt << 5;
    const size_t base = ((size_t)b * SEQ) * D_MODEL + h * 64;

#pragma unroll
    for (int i = 0; i < 4; i++) {
        int idx = tid + (i << 7);
        int r = idx >> 4, c = (idx & 15) << 2;
        float4 t = *(const float4*)(Q + base + (size_t)(q0 + r) * D_MODEL + c);
        *(float4*)&Qs[r][c ^ ((r & 4) << 2)] = t;
    }

    float acc[4][4];
    float mi[4], li[4];
#pragma unroll
    for (int i = 0; i < 4; i++) {
        mi[i] = -1e30f; li[i] = 0.f;
#pragma unroll
        for (int j = 0; j < 4; j++) acc[i][j] = 0.f;
    }

    const int ntiles = (q0 + 95) >> 6;
    for (int t = 0; t < ntiles; t++) {
        const int j0 = t << 6;
        __syncthreads();
#pragma unroll
        for (int i = 0; i < 8; i++) {
            int idx = tid + (i << 7);
            int r = idx >> 4, c = (idx & 15) << 2;
            float4 kf = *(const float4*)(K + base + (size_t)(j0 + r) * D_MODEL + c);
            int jc = r ^ c;
            Kt[c + 0][jc] = kf.x;
            Kt[c + 1][jc] = kf.y;
            Kt[c + 2][jc] = kf.z;
            Kt[c + 3][jc] = kf.w;
            float4 vf = *(const float4*)(V + base + (size_t)(j0 + r) * D_MODEL + c);
            *(float4*)&Vs[r][c] = vf;
        }
        __syncthreads();

        float s[4][4];
#pragma unroll
        for (int i = 0; i < 4; i++)
#pragma unroll
            for (int j = 0; j < 4; j++) s[i][j] = 0.f;

#pragma unroll
        for (int k4 = 0; k4 < 16; k4++) {
            const int kc = k4 << 2;
            float4 qf[4], kf[4];
#pragma unroll
            for (int i = 0; i < 4; i++) {
                int row = ty * 4 + i;
                qf[i] = *(const float4*)&Qs[row][kc ^ ((row & 4) << 2)];
            }
#pragma unroll
            for (int u = 0; u < 4; u++)
                kf[u] = *(const float4*)&Kt[kc + u][(tx << 2) ^ kc];
#pragma unroll
            for (int i = 0; i < 4; i++) {
                const float* qv = (const float*)&qf[i];
#pragma unroll
                for (int u = 0; u < 4; u++) {
                    float qa = qv[u];
                    s[i][0] = fmaf(qa, kf[u].x, s[i][0]);
                    s[i][1] = fmaf(qa, kf[u].y, s[i][1]);
                    s[i][2] = fmaf(qa, kf[u].z, s[i][2]);
                    s[i][3] = fmaf(qa, kf[u].w, s[i][3]);
                }
            }
        }

        const bool maskTile = (t == ntiles - 1);
#pragma unroll
        for (int i = 0; i < 4; i++) {
            int row = ty * 4 + i;
            int qg = q0 + row;
#pragma unroll
            for (int j = 0; j < 4; j++) {
                float sv = s[i][j] * 0.125f;
                if (maskTile && (j0 + (tx << 2) + j > qg)) sv = -1e30f;
                s[i][j] = sv;
            }
            float rmax = fmaxf(fmaxf(s[i][0], s[i][1]), fmaxf(s[i][2], s[i][3]));
#pragma unroll
            for (int off = 8; off > 0; off >>= 1)
                rmax = fmaxf(rmax, __shfl_xor_sync(0xffffffffu, rmax, off));
            float mnew = fmaxf(mi[i], rmax);
            float corr = __expf(mi[i] - mnew);
            mi[i] = mnew;
            float rsum = 0.f;
#pragma unroll
            for (int j = 0; j < 4; j++) {
                float p = __expf(s[i][j] - mnew);
                s[i][j] = p;
                rsum += p;
            }
#pragma unroll
            for (int off = 8; off > 0; off >>= 1)
                rsum += __shfl_xor_sync(0xffffffffu, rsum, off);
            li[i] = li[i] * corr + rsum;
#pragma unroll
            for (int j = 0; j < 4; j++) acc[i][j] *= corr;
            *(float4*)&Ps[row][(tx << 2) ^ ((row & 4) << 2)] = *(float4*)&s[i][0];
        }
        __syncthreads();

#pragma unroll
        for (int j4 = 0; j4 < 16; j4++) {
            const int jc = j4 << 2;
            float4 pf[4], vf[4];
#pragma unroll
            for (int i = 0; i < 4; i++) {
                int row = ty * 4 + i;
                pf[i] = *(const float4*)&Ps[row][jc ^ ((row & 4) << 2)];
            }
#pragma unroll
            for (int u = 0; u < 4; u++)
                vf[u] = *(const float4*)&Vs[jc + u][tx << 2];
#pragma unroll
            for (int i = 0; i < 4; i++) {
                const float* pv = (const float*)&pf[i];
#pragma unroll
                for (int u = 0; u < 4; u++) {
                    float pa = pv[u];
                    acc[i][0] = fmaf(pa, vf[u].x, acc[i][0]);
                    acc[i][1] = fmaf(pa, vf[u].y, acc[i][1]);
                    acc[i][2] = fmaf(pa, vf[u].z, acc[i][2]);
                    acc[i][3] = fmaf(pa, vf[u].w, acc[i][3]);
                }
            }
        }
    }

#pragma unroll
    for (int i = 0; i < 4; i++) {
        float inv = 1.f / li[i];
        float4 r;
        r.x = acc[i][0] * inv; r.y = acc[i][1] * inv;
        r.z = acc[i][2] * inv; r.w = acc[i][3] * inv;
        *(float4*)(O + base + (size_t)(q0 + ty * 4 + i) * D_MODEL + (tx << 2)) = r;
    }
}

// ---------------------------------------------------------------------------
extern "C" void kernel_launch(void* const* d_in, const int* in_sizes, int n_in,
                              void* d_out, int out_size)
{
    const float* x   = (const float*)d_in[0];
    const float* pos = (const float*)d_in[1];
    const float* Wq  = (const float*)d_in[2];
    const float* bq  = (const float*)d_in[3];
    const float* Wk  = (const float*)d_in[4];
    const float* bk  = (const float*)d_in[5];
    const float* Wv  = (const float*)d_in[6];
    const float* bv  = (const float*)d_in[7];
    const float* Wp  = (const float*)d_in[8];
    const float* bp  = (const float*)d_in[9];
    const float* Wo  = (const float*)d_in[10];
    const float* bo  = (const float*)d_in[11];
    float* out = (float*)d_out;

    float *q, *k, *v, *ctx, *p;
    cudaGetSymbolAddress((void**)&q,   g_q);
    cudaGetSymbolAddress((void**)&k,   g_k);
    cudaGetSymbolAddress((void**)&v,   g_v);
    cudaGetSymbolAddress((void**)&ctx, g_ctx);
    cudaGetSymbolAddress((void**)&p,   g_p);

    static bool attr_done = false;
    if (!attr_done) {
        cudaFuncSetAttribute(gemm_mma_kernel,
                             cudaFuncAttributeMaxDynamicSharedMemorySize, SM_TOTAL);
        attr_done = true;
    }

    dim3 blk(256);
    dim3 gP(D_MODEL / BN, SEQ / BM);    // (8, 16)
    dim3 gX(D_MODEL / BN, NTOK / BM);   // (8, 64)

    gemm_mma_kernel<<<gP, blk, SM_TOTAL>>>(pos, Wp, bp, nullptr, p, 0);
    gemm_mma_kernel<<<gX, blk, SM_TOTAL>>>(x, Wq, bq, p, q, 1);
    gemm_mma_kernel<<<gX, blk, SM_TOTAL>>>(x, Wk, bk, nullptr, k, 0);
    gemm_mma_kernel<<<gX, blk, SM_TOTAL>>>(x, Wv, bv, nullptr, v, 0);
    flash_attn_kernel<<<dim3(SEQ / 32, BATCH * 16), 128>>>(q, k, v, ctx);
    gemm_mma_kernel<<<gX, blk, SM_TOTAL>>>(ctx, Wo, bo, nullptr, out, 0);
}

// round 4
// speedup vs baseline: 1.9074x; 1.0009x over previous
#include <cuda_runtime.h>
#include <cstdint>
#include <math.h>

#define D_MODEL 1024
#define SEQ     2048
#define BATCH   4
#define NTOK    (BATCH * SEQ)   /* 8192 */

// ---------------- scratch (device globals; no allocations allowed) ----------
__device__ float g_q[NTOK * D_MODEL];
__device__ float g_k[NTOK * D_MODEL];
__device__ float g_v[NTOK * D_MODEL];
__device__ float g_ctx[NTOK * D_MODEL];
__device__ float g_p[SEQ * D_MODEL];

// ============================ helpers =======================================
#define CP_ASYNC16(dst, src) \
    asm volatile("cp.async.cg.shared.global [%0], [%1], 16;" \
                 :: "r"(dst), "l"(src) : "memory")
#define CP_COMMIT() asm volatile("cp.async.commit_group;" ::: "memory")
#define CP_WAIT(n)  asm volatile("cp.async.wait_group %0;" :: "n"(n) : "memory")

#define SW128(off) ((off) ^ (((off) >> 3) & 0x70))

__device__ __forceinline__ uint32_t smem_u32(const void* p) {
    uint32_t a;
    asm("{ .reg .u64 t; cvta.to.shared.u64 t, %1; cvt.u32.u64 %0, t; }"
        : "=r"(a) : "l"(p));
    return a;
}

__device__ __forceinline__ uint32_t f2tf32(float f) {
    uint32_t r;
    asm("cvt.rna.tf32.f32 %0, %1;" : "=r"(r) : "f"(f));
    return r;
}

#define MMA_TF32(c0, c1, c2, c3, a0, a1, a2, a3, b0, b1) \
    asm volatile( \
        "mma.sync.aligned.m16n8k8.row.col.f32.tf32.tf32.f32 " \
        "{%0,%1,%2,%3}, {%4,%5,%6,%7}, {%8,%9}, {%0,%1,%2,%3};" \
        : "+f"(c0), "+f"(c1), "+f"(c2), "+f"(c3) \
        : "r"(a0), "r"(a1), "r"(a2), "r"(a3), "r"(b0), "r"(b1))

// ============================ mma.sync tf32 GEMM ============================
// Y[m,n] = sum_k X[m,k]*W[n,k] + bias[n] (+ P[m mod SEQ, n] if addP)
// Tile 128x128x32, 8 warps (2 M x 4 N), warp tile 64x32 (4 mfrag x 4 nfrag),
// 4-stage cp.async pipeline, SW128-swizzled smem, fragments via scalar LDS.
#define BM 128
#define BN 128
#define BK 32
#define GSTAGES 4
#define NCHUNK (D_MODEL / BK)      /* 32 */
#define TILE_B (BM * BK * 4)       /* 16384 bytes, same for A and B */
#define STG_B  (2 * TILE_B)        /* 32768 per stage */
#define SM_TOTAL (GSTAGES * STG_B) /* 131072 */

__device__ __forceinline__ float lds_sw(const char* base, int r, int c) {
    return *(const float*)(base + SW128(r * 128 + c * 4));
}

__device__ __forceinline__ void gemm_load_chunk(
    const float* __restrict__ X, const float* __restrict__ W,
    uint32_t sbase, int stage, int m0, int n0, int kof, int tid)
{
    const uint32_t abase = sbase + stage * STG_B;
    const uint32_t bbase = abase + TILE_B;
#pragma unroll
    for (int i = 0; i < 4; i++) {
        int seg = tid + (i << 8);
        int row = seg >> 3, c16 = seg & 7;
        uint32_t off = row * 128 + c16 * 16;
        CP_ASYNC16(abase + SW128(off),
                   X + (size_t)(m0 + row) * D_MODEL + kof + c16 * 4);
    }
#pragma unroll
    for (int i = 0; i < 4; i++) {
        int seg = tid + (i << 8);
        int row = seg >> 3, c16 = seg & 7;
        uint32_t off = row * 128 + c16 * 16;
        CP_ASYNC16(bbase + SW128(off),
                   W + (size_t)(n0 + row) * D_MODEL + kof + c16 * 4);
    }
}

__global__ __launch_bounds__(256, 1) void gemm_mma_kernel(
    const float* __restrict__ X, const float* __restrict__ W,
    const float* __restrict__ bias, const float* __restrict__ P,
    float* __restrict__ Y, int addP)
{
    extern __shared__ char smem[];
    const uint32_t sb = smem_u32(smem);
    const int tid = threadIdx.x;
    const int lane = tid & 31, wid = tid >> 5;
    const int wm = wid >> 2;          // 0..1
    const int wn = wid & 3;           // 0..3
    const int n0 = blockIdx.x * BN;
    const int m0 = blockIdx.y * BM;

    float acc[4][4][4];
#pragma unroll
    for (int f = 0; f < 4; f++)
#pragma unroll
        for (int g = 0; g < 4; g++)
#pragma unroll
            for (int e = 0; e < 4; e++) acc[f][g][e] = 0.f;

    // prologue: stages 0..2
#pragma unroll
    for (int c = 0; c < GSTAGES - 1; c++) {
        gemm_load_chunk(X, W, sb, c, m0, n0, c * BK, tid);
        CP_COMMIT();
    }

    const int lq = lane >> 2;   // 0..7
    const int lr = lane & 3;    // 0..3

    for (int m = 0; m < NCHUNK; m++) {
        CP_WAIT(GSTAGES - 2);
        __syncthreads();

        const int pc = m + GSTAGES - 1;
        if (pc < NCHUNK)
            gemm_load_chunk(X, W, sb, pc & (GSTAGES - 1), m0, n0, pc * BK, tid);
        CP_COMMIT();

        const char* as = smem + (m & (GSTAGES - 1)) * STG_B;
        const char* bs = as + TILE_B;
#pragma unroll
        for (int ks = 0; ks < 4; ks++) {
            const int kc = ks * 8 + lr;
            uint32_t A[4][4];
#pragma unroll
            for (int f = 0; f < 4; f++) {
                const int r = wm * 64 + f * 16 + lq;
                A[f][0] = f2tf32(lds_sw(as, r,     kc));
                A[f][1] = f2tf32(lds_sw(as, r + 8, kc));
                A[f][2] = f2tf32(lds_sw(as, r,     kc + 4));
                A[f][3] = f2tf32(lds_sw(as, r + 8, kc + 4));
            }
            uint32_t B[4][2];
#pragma unroll
            for (int g = 0; g < 4; g++) {
                const int n = wn * 32 + g * 8 + lq;
                B[g][0] = f2tf32(lds_sw(bs, n, kc));
                B[g][1] = f2tf32(lds_sw(bs, n, kc + 4));
            }
#pragma unroll
            for (int f = 0; f < 4; f++)
#pragma unroll
                for (int g = 0; g < 4; g++)
                    MMA_TF32(acc[f][g][0], acc[f][g][1], acc[f][g][2], acc[f][g][3],
                             A[f][0], A[f][1], A[f][2], A[f][3],
                             B[g][0], B[g][1]);
        }
    }

    // epilogue: C frag rows (lq, lq+8), cols 2*lr, 2*lr+1 -> float2 stores
#pragma unroll
    for (int f = 0; f < 4; f++) {
        const int r0 = m0 + wm * 64 + f * 16 + lq;
#pragma unroll
        for (int g = 0; g < 4; g++) {
            const int nc = n0 + wn * 32 + g * 8 + 2 * lr;
            float2 bz = *(const float2*)(bias + nc);
            float2 v0, v1;
            v0.x = acc[f][g][0] + bz.x; v0.y = acc[f][g][1] + bz.y;
            v1.x = acc[f][g][2] + bz.x; v1.y = acc[f][g][3] + bz.y;
            if (addP) {
                float2 p0 = *(const float2*)(P + (size_t)(r0 & (SEQ - 1)) * D_MODEL + nc);
                float2 p1 = *(const float2*)(P + (size_t)((r0 + 8) & (SEQ - 1)) * D_MODEL + nc);
                v0.x += p0.x; v0.y += p0.y;
                v1.x += p1.x; v1.y += p1.y;
            }
            *(float2*)(Y + (size_t)r0 * D_MODEL + nc) = v0;
            *(float2*)(Y + (size_t)(r0 + 8) * D_MODEL + nc) = v1;
        }
    }
}

// ---------------------------------------------------------------------------
// Flash attention, fp32, causal (unchanged from R1 passing version).
// ---------------------------------------------------------------------------
__global__ __launch_bounds__(128) void flash_attn_kernel(
    const float* __restrict__ Q, const float* __restrict__ K,
    const float* __restrict__ V, float* __restrict__ O)
{
    __shared__ float Qs[32][64];
    __shared__ float Kt[64][64];
    __shared__ float Vs[64][64];
    __shared__ float Ps[32][64];

    const int tid = threadIdx.x;
    const int tx = tid & 15, ty = tid >> 4;
    const int qt = blockIdx.x;
    const int bh = blockIdx.y;
    const int b = bh >> 4, h = bh & 15;
    const int q0 = qt << 5;
    const size_t base = ((size_t)b * SEQ) * D_MODEL + h * 64;

#pragma unroll
    for (int i = 0; i < 4; i++) {
        int idx = tid + (i << 7);
        int r = idx >> 4, c = (idx & 15) << 2;
        float4 t = *(const float4*)(Q + base + (size_t)(q0 + r) * D_MODEL + c);
        *(float4*)&Qs[r][c ^ ((r & 4) << 2)] = t;
    }

    float acc[4][4];
    float mi[4], li[4];
#pragma unroll
    for (int i = 0; i < 4; i++) {
        mi[i] = -1e30f; li[i] = 0.f;
#pragma unroll
        for (int j = 0; j < 4; j++) acc[i][j] = 0.f;
    }

    const int ntiles = (q0 + 95) >> 6;
    for (int t = 0; t < ntiles; t++) {
        const int j0 = t << 6;
        __syncthreads();
#pragma unroll
        for (int i = 0; i < 8; i++) {
            int idx = tid + (i << 7);
            int r = idx >> 4, c = (idx & 15) << 2;
            float4 kf = *(const float4*)(K + base + (size_t)(j0 + r) * D_MODEL + c);
            int jc = r ^ c;
            Kt[c + 0][jc] = kf.x;
            Kt[c + 1][jc] = kf.y;
            Kt[c + 2][jc] = kf.z;
            Kt[c + 3][jc] = kf.w;
            float4 vf = *(const float4*)(V + base + (size_t)(j0 + r) * D_MODEL + c);
            *(float4*)&Vs[r][c] = vf;
        }
        __syncthreads();

        float s[4][4];
#pragma unroll
        for (int i = 0; i < 4; i++)
#pragma unroll
            for (int j = 0; j < 4; j++) s[i][j] = 0.f;

#pragma unroll
        for (int k4 = 0; k4 < 16; k4++) {
            const int kc = k4 << 2;
            float4 qf[4], kf[4];
#pragma unroll
            for (int i = 0; i < 4; i++) {
                int row = ty * 4 + i;
                qf[i] = *(const float4*)&Qs[row][kc ^ ((row & 4) << 2)];
            }
#pragma unroll
            for (int u = 0; u < 4; u++)
                kf[u] = *(const float4*)&Kt[kc + u][(tx << 2) ^ kc];
#pragma unroll
            for (int i = 0; i < 4; i++) {
                const float* qv = (const float*)&qf[i];
#pragma unroll
                for (int u = 0; u < 4; u++) {
                    float qa = qv[u];
                    s[i][0] = fmaf(qa, kf[u].x, s[i][0]);
                    s[i][1] = fmaf(qa, kf[u].y, s[i][1]);
                    s[i][2] = fmaf(qa, kf[u].z, s[i][2]);
                    s[i][3] = fmaf(qa, kf[u].w, s[i][3]);
                }
            }
        }

        const bool maskTile = (t == ntiles - 1);
#pragma unroll
        for (int i = 0; i < 4; i++) {
            int row = ty * 4 + i;
            int qg = q0 + row;
#pragma unroll
            for (int j = 0; j < 4; j++) {
                float sv = s[i][j] * 0.125f;
                if (maskTile && (j0 + (tx << 2) + j > qg)) sv = -1e30f;
                s[i][j] = sv;
            }
            float rmax = fmaxf(fmaxf(s[i][0], s[i][1]), fmaxf(s[i][2], s[i][3]));
#pragma unroll
            for (int off = 8; off > 0; off >>= 1)
                rmax = fmaxf(rmax, __shfl_xor_sync(0xffffffffu, rmax, off));
            float mnew = fmaxf(mi[i], rmax);
            float corr = __expf(mi[i] - mnew);
            mi[i] = mnew;
            float rsum = 0.f;
#pragma unroll
            for (int j = 0; j < 4; j++) {
                float p = __expf(s[i][j] - mnew);
                s[i][j] = p;
                rsum += p;
            }
#pragma unroll
            for (int off = 8; off > 0; off >>= 1)
                rsum += __shfl_xor_sync(0xffffffffu, rsum, off);
            li[i] = li[i] * corr + rsum;
#pragma unroll
            for (int j = 0; j < 4; j++) acc[i][j] *= corr;
            *(float4*)&Ps[row][(tx << 2) ^ ((row & 4) << 2)] = *(float4*)&s[i][0];
        }
        __syncthreads();

#pragma unroll
        for (int j4 = 0; j4 < 16; j4++) {
            const int jc = j4 << 2;
            float4 pf[4], vf[4];
#pragma unroll
            for (int i = 0; i < 4; i++) {
                int row = ty * 4 + i;
                pf[i] = *(const float4*)&Ps[row][jc ^ ((row & 4) << 2)];
            }
#pragma unroll
            for (int u = 0; u < 4; u++)
                vf[u] = *(const float4*)&Vs[jc + u][tx << 2];
#pragma unroll
            for (int i = 0; i < 4; i++) {
                const float* pv = (const float*)&pf[i];
#pragma unroll
                for (int u = 0; u < 4; u++) {
                    float pa = pv[u];
                    acc[i][0] = fmaf(pa, vf[u].x, acc[i][0]);
                    acc[i][1] = fmaf(pa, vf[u].y, acc[i][1]);
                    acc[i][2] = fmaf(pa, vf[u].z, acc[i][2]);
                    acc[i][3] = fmaf(pa, vf[u].w, acc[i][3]);
                }
            }
        }
    }

#pragma unroll
    for (int i = 0; i < 4; i++) {
        float inv = 1.f / li[i];
        float4 r;
        r.x = acc[i][0] * inv; r.y = acc[i][1] * inv;
        r.z = acc[i][2] * inv; r.w = acc[i][3] * inv;
        *(float4*)(O + base + (size_t)(q0 + ty * 4 + i) * D_MODEL + (tx << 2)) = r;
    }
}

// ---------------------------------------------------------------------------
extern "C" void kernel_launch(void* const* d_in, const int* in_sizes, int n_in,
                              void* d_out, int out_size)
{
    const float* x   = (const float*)d_in[0];
    const float* pos = (const float*)d_in[1];
    const float* Wq  = (const float*)d_in[2];
    const float* bq  = (const float*)d_in[3];
    const float* Wk  = (const float*)d_in[4];
    const float* bk  = (const float*)d_in[5];
    const float* Wv  = (const float*)d_in[6];
    const float* bv  = (const float*)d_in[7];
    const float* Wp  = (const float*)d_in[8];
    const float* bp  = (const float*)d_in[9];
    const float* Wo  = (const float*)d_in[10];
    const float* bo  = (const float*)d_in[11];
    float* out = (float*)d_out;

    float *q, *k, *v, *ctx, *p;
    cudaGetSymbolAddress((void**)&q,   g_q);
    cudaGetSymbolAddress((void**)&k,   g_k);
    cudaGetSymbolAddress((void**)&v,   g_v);
    cudaGetSymbolAddress((void**)&ctx, g_ctx);
    cudaGetSymbolAddress((void**)&p,   g_p);

    static bool attr_done = false;
    if (!attr_done) {
        cudaFuncSetAttribute(gemm_mma_kernel,
                             cudaFuncAttributeMaxDynamicSharedMemorySize, SM_TOTAL);
        attr_done = true;
    }

    dim3 blk(256);
    dim3 gP(D_MODEL / BN, SEQ / BM);    // (8, 16)
    dim3 gX(D_MODEL / BN, NTOK / BM);   // (8, 64)

    gemm_mma_kernel<<<gP, blk, SM_TOTAL>>>(pos, Wp, bp, nullptr, p, 0);
    gemm_mma_kernel<<<gX, blk, SM_TOTAL>>>(x, Wq, bq, p, q, 1);
    gemm_mma_kernel<<<gX, blk, SM_TOTAL>>>(x, Wk, bk, nullptr, k, 0);
    gemm_mma_kernel<<<gX, blk, SM_TOTAL>>>(x, Wv, bv, nullptr, v, 0);
    flash_attn_kernel<<<dim3(SEQ / 32, BATCH * 16), 128>>>(q, k, v, ctx);
    gemm_mma_kernel<<<gX, blk, SM_TOTAL>>>(ctx, Wo, bo, nullptr, out, 0);
}

// round 5
// speedup vs baseline: 3.5438x; 1.8579x over previous
#include <cuda_runtime.h>
#include <cstdint>
#include <math.h>

#define D_MODEL 1024
#define SEQ     2048
#define BATCH   4
#define NTOK    (BATCH * SEQ)   /* 8192 */

// ---------------- scratch (device globals; no allocations allowed) ----------
__device__ float g_q[NTOK * D_MODEL];
__device__ float g_k[NTOK * D_MODEL];
__device__ float g_v[NTOK * D_MODEL];
__device__ float g_ctx[NTOK * D_MODEL];
__device__ float g_p[SEQ * D_MODEL];

// ============================ helpers =======================================
#define CP_ASYNC16(dst, src) \
    asm volatile("cp.async.cg.shared.global [%0], [%1], 16;" \
                 :: "r"(dst), "l"(src) : "memory")
#define CP_COMMIT() asm volatile("cp.async.commit_group;" ::: "memory")
#define CP_WAIT(n)  asm volatile("cp.async.wait_group %0;" :: "n"(n) : "memory")

#define SW128(off) ((off) ^ (((off) >> 3) & 0x70))

__device__ __forceinline__ uint32_t smem_u32(const void* p) {
    uint32_t a;
    asm("{ .reg .u64 t; cvta.to.shared.u64 t, %1; cvt.u32.u64 %0, t; }"
        : "=r"(a) : "l"(p));
    return a;
}

__device__ __forceinline__ uint32_t f2tf32(float f) {
    uint32_t r;
    asm("cvt.rna.tf32.f32 %0, %1;" : "=r"(r) : "f"(f));
    return r;
}

#define MMA_TF32(c0, c1, c2, c3, a0, a1, a2, a3, b0, b1) \
    asm volatile( \
        "mma.sync.aligned.m16n8k8.row.col.f32.tf32.tf32.f32 " \
        "{%0,%1,%2,%3}, {%4,%5,%6,%7}, {%8,%9}, {%0,%1,%2,%3};" \
        : "+f"(c0), "+f"(c1), "+f"(c2), "+f"(c3) \
        : "r"(a0), "r"(a1), "r"(a2), "r"(a3), "r"(b0), "r"(b1))

// ============================ mma.sync tf32 GEMM ============================
// Y[m,n] = sum_k X[m,k]*W[n,k] + bias[n] (+ P[m mod SEQ, n] if addP)
// If roundOut: output rounded to tf32 (so attention can skip operand cvts).
#define BM 128
#define BN 128
#define BK 32
#define GSTAGES 4
#define NCHUNK (D_MODEL / BK)      /* 32 */
#define TILE_B (BM * BK * 4)       /* 16384 bytes, same for A and B */
#define STG_B  (2 * TILE_B)        /* 32768 per stage */
#define SM_TOTAL (GSTAGES * STG_B) /* 131072 */

__device__ __forceinline__ float lds_sw(const char* base, int r, int c) {
    return *(const float*)(base + SW128(r * 128 + c * 4));
}

__device__ __forceinline__ void gemm_load_chunk(
    const float* __restrict__ X, const float* __restrict__ W,
    uint32_t sbase, int stage, int m0, int n0, int kof, int tid)
{
    const uint32_t abase = sbase + stage * STG_B;
    const uint32_t bbase = abase + TILE_B;
#pragma unroll
    for (int i = 0; i < 4; i++) {
        int seg = tid + (i << 8);
        int row = seg >> 3, c16 = seg & 7;
        uint32_t off = row * 128 + c16 * 16;
        CP_ASYNC16(abase + SW128(off),
                   X + (size_t)(m0 + row) * D_MODEL + kof + c16 * 4);
    }
#pragma unroll
    for (int i = 0; i < 4; i++) {
        int seg = tid + (i << 8);
        int row = seg >> 3, c16 = seg & 7;
        uint32_t off = row * 128 + c16 * 16;
        CP_ASYNC16(bbase + SW128(off),
                   W + (size_t)(n0 + row) * D_MODEL + kof + c16 * 4);
    }
}

__global__ __launch_bounds__(256, 1) void gemm_mma_kernel(
    const float* __restrict__ X, const float* __restrict__ W,
    const float* __restrict__ bias, const float* __restrict__ P,
    float* __restrict__ Y, int addP, int roundOut)
{
    extern __shared__ char smem[];
    const uint32_t sb = smem_u32(smem);
    const int tid = threadIdx.x;
    const int lane = tid & 31, wid = tid >> 5;
    const int wm = wid >> 2;          // 0..1
    const int wn = wid & 3;           // 0..3
    const int n0 = blockIdx.x * BN;
    const int m0 = blockIdx.y * BM;

    float acc[4][4][4];
#pragma unroll
    for (int f = 0; f < 4; f++)
#pragma unroll
        for (int g = 0; g < 4; g++)
#pragma unroll
            for (int e = 0; e < 4; e++) acc[f][g][e] = 0.f;

#pragma unroll
    for (int c = 0; c < GSTAGES - 1; c++) {
        gemm_load_chunk(X, W, sb, c, m0, n0, c * BK, tid);
        CP_COMMIT();
    }

    const int lq = lane >> 2;   // 0..7
    const int lr = lane & 3;    // 0..3

    for (int m = 0; m < NCHUNK; m++) {
        CP_WAIT(GSTAGES - 2);
        __syncthreads();

        const int pc = m + GSTAGES - 1;
        if (pc < NCHUNK)
            gemm_load_chunk(X, W, sb, pc & (GSTAGES - 1), m0, n0, pc * BK, tid);
        CP_COMMIT();

        const char* as = smem + (m & (GSTAGES - 1)) * STG_B;
        const char* bs = as + TILE_B;
#pragma unroll
        for (int ks = 0; ks < 4; ks++) {
            const int kc = ks * 8 + lr;
            uint32_t A[4][4];
#pragma unroll
            for (int f = 0; f < 4; f++) {
                const int r = wm * 64 + f * 16 + lq;
                A[f][0] = f2tf32(lds_sw(as, r,     kc));
                A[f][1] = f2tf32(lds_sw(as, r + 8, kc));
                A[f][2] = f2tf32(lds_sw(as, r,     kc + 4));
                A[f][3] = f2tf32(lds_sw(as, r + 8, kc + 4));
            }
            uint32_t B[4][2];
#pragma unroll
            for (int g = 0; g < 4; g++) {
                const int n = wn * 32 + g * 8 + lq;
                B[g][0] = f2tf32(lds_sw(bs, n, kc));
                B[g][1] = f2tf32(lds_sw(bs, n, kc + 4));
            }
#pragma unroll
            for (int f = 0; f < 4; f++)
#pragma unroll
                for (int g = 0; g < 4; g++)
                    MMA_TF32(acc[f][g][0], acc[f][g][1], acc[f][g][2], acc[f][g][3],
                             A[f][0], A[f][1], A[f][2], A[f][3],
                             B[g][0], B[g][1]);
        }
    }

#pragma unroll
    for (int f = 0; f < 4; f++) {
        const int r0 = m0 + wm * 64 + f * 16 + lq;
#pragma unroll
        for (int g = 0; g < 4; g++) {
            const int nc = n0 + wn * 32 + g * 8 + 2 * lr;
            float2 bz = *(const float2*)(bias + nc);
            float2 v0, v1;
            v0.x = acc[f][g][0] + bz.x; v0.y = acc[f][g][1] + bz.y;
            v1.x = acc[f][g][2] + bz.x; v1.y = acc[f][g][3] + bz.y;
            if (addP) {
                float2 p0 = *(const float2*)(P + (size_t)(r0 & (SEQ - 1)) * D_MODEL + nc);
                float2 p1 = *(const float2*)(P + (size_t)((r0 + 8) & (SEQ - 1)) * D_MODEL + nc);
                v0.x += p0.x; v0.y += p0.y;
                v1.x += p1.x; v1.y += p1.y;
            }
            if (roundOut) {
                v0.x = __uint_as_float(f2tf32(v0.x));
                v0.y = __uint_as_float(f2tf32(v0.y));
                v1.x = __uint_as_float(f2tf32(v1.x));
                v1.y = __uint_as_float(f2tf32(v1.y));
            }
            *(float2*)(Y + (size_t)r0 * D_MODEL + nc) = v0;
            *(float2*)(Y + (size_t)(r0 + 8) * D_MODEL + nc) = v1;
        }
    }
}

// ============================ mma.sync flash attention ======================
// BQ=128 (8 warps x m16), BJ=64, dk=64. Q frags in regs; K/V double-buffered
// cp.async; P relayout via per-warp smem. q/k/v pre-rounded to tf32 by the
// projection epilogue, so operands feed MMA as raw bits (no cvt).
#define BQ 128
#define BJ 64
#define KV_F   (BJ * 64)                 /* 4096 floats / stage */
#define AV_OFF (2 * KV_F)                /* V stages after K stages */
#define AP_OFF (4 * KV_F)                /* P after V */
#define ATT_SMEM ((4 * KV_F + 8 * 16 * 64) * 4)  /* 98304 B */

__global__ __launch_bounds__(256, 1) void flash_mma_kernel(
    const float* __restrict__ Q, const float* __restrict__ K,
    const float* __restrict__ V, float* __restrict__ O)
{
    extern __shared__ char smem[];
    float* smf = (float*)smem;
    const int tid = threadIdx.x;
    const int lane = tid & 31, w = tid >> 5;
    const int lq = lane >> 2, lr = lane & 3;
    const int qt = gridDim.x - 1 - blockIdx.x;   // heavy tiles first
    const int bh = blockIdx.y;
    const int b = bh >> 4, h = bh & 15;
    const int q0 = qt * BQ;
    const size_t base = ((size_t)b * SEQ) * D_MODEL + h * 64;
    const uint32_t sb = smem_u32(smem);

    uint32_t* Pw = (uint32_t*)(smf + AP_OFF + w * (16 * 64));
    const int swn = lq << 2;      // K/P swizzle amount (row&7 == lq)
    const int swv = lr << 3;      // V swizzle amount ((kc&3) == lr)

    // Q fragments (already tf32-rounded in gmem; *0.125 is exact)
    uint32_t qa[8][4];
    {
        const float* q0p = Q + base + (size_t)(q0 + w * 16 + lq) * D_MODEL;
        const float* q1p = q0p + 8 * D_MODEL;
#pragma unroll
        for (int ks = 0; ks < 8; ks++) {
            const int c = ks * 8 + lr;
            qa[ks][0] = __float_as_uint(q0p[c] * 0.125f);
            qa[ks][1] = __float_as_uint(q1p[c] * 0.125f);
            qa[ks][2] = __float_as_uint(q0p[c + 4] * 0.125f);
            qa[ks][3] = __float_as_uint(q1p[c + 4] * 0.125f);
        }
    }

    float o[8][4];
#pragma unroll
    for (int g = 0; g < 8; g++)
#pragma unroll
        for (int e = 0; e < 4; e++) o[g][e] = 0.f;
    float m0 = -1e30f, m1 = -1e30f, l0 = 0.f, l1 = 0.f;

    const int nj = qt * 2 + 2;

    // K/V tile loader: stage s = t&1
#define LOAD_KV(t_) do {                                                      \
    const int s_ = (t_) & 1;                                                  \
    const float* kg = K + base + (size_t)((t_) * BJ) * D_MODEL;               \
    const float* vg = V + base + (size_t)((t_) * BJ) * D_MODEL;               \
    const uint32_t kb = sb + s_ * (KV_F * 4);                                 \
    const uint32_t vb = sb + (AV_OFF + s_ * KV_F) * 4;                        \
    _Pragma("unroll")                                                         \
    for (int i_ = 0; i_ < 4; i_++) {                                          \
        int seg = tid + (i_ << 8);                                            \
        int row = seg >> 4, c4 = seg & 15;                                    \
        uint32_t kfi = row * 64 + ((c4 * 4) ^ ((row & 7) << 2));              \
        uint32_t vfi = row * 64 + ((c4 * 4) ^ ((row & 3) << 3));              \
        CP_ASYNC16(kb + kfi * 4, kg + (size_t)row * D_MODEL + c4 * 4);        \
        CP_ASYNC16(vb + vfi * 4, vg + (size_t)row * D_MODEL + c4 * 4);        \
    }                                                                         \
} while (0)

    LOAD_KV(0);
    CP_COMMIT();

    const int qw = q0 + w * 16;        // warp's first q row
    const int qmax = qw + 15;

    for (int t = 0; t < nj; t++) {
        CP_WAIT(0);
        __syncthreads();
        if (t + 1 < nj) { LOAD_KV(t + 1); CP_COMMIT(); }

        const float* ks_ = smf + (t & 1) * KV_F;
        const float* vs_ = smf + AV_OFF + (t & 1) * KV_F;
        const int j0 = t * BJ;

        // ---- S = Q K^T (skip n-frags fully above the diagonal) ----
        float s[8][4];
        unsigned act = 0;
#pragma unroll
        for (int g = 0; g < 8; g++) {
            bool a = (j0 + g * 8) <= qmax;
            if (a) act |= 1u << g;
            float init = a ? 0.f : -1e30f;
            s[g][0] = init; s[g][1] = init; s[g][2] = init; s[g][3] = init;
        }
#pragma unroll
        for (int ks = 0; ks < 8; ks++) {
            const int kc = ks * 8 + lr;
#pragma unroll
            for (int g = 0; g < 8; g++) {
                if (!((act >> g) & 1)) continue;
                const int nrow = (g * 8 + lq) * 64;
                uint32_t b0 = __float_as_uint(ks_[nrow + (kc ^ swn)]);
                uint32_t b1 = __float_as_uint(ks_[nrow + ((kc + 4) ^ swn)]);
                MMA_TF32(s[g][0], s[g][1], s[g][2], s[g][3],
                         qa[ks][0], qa[ks][1], qa[ks][2], qa[ks][3], b0, b1);
            }
        }

        // ---- causal element mask (diagonal tiles only) ----
        if (j0 + BJ - 1 > qw) {
            const int Q0 = qw + lq, Q1 = Q0 + 8;
#pragma unroll
            for (int g = 0; g < 8; g++) {
                const int jc = j0 + g * 8 + 2 * lr;
                if (jc     > Q0) s[g][0] = -1e30f;
                if (jc + 1 > Q0) s[g][1] = -1e30f;
                if (jc     > Q1) s[g][2] = -1e30f;
                if (jc + 1 > Q1) s[g][3] = -1e30f;
            }
        }

        // ---- online softmax (rows lq / lq+8; reduce over 4 lr lanes) ----
        float mx0 = -1e30f, mx1 = -1e30f;
#pragma unroll
        for (int g = 0; g < 8; g++) {
            mx0 = fmaxf(mx0, fmaxf(s[g][0], s[g][1]));
            mx1 = fmaxf(mx1, fmaxf(s[g][2], s[g][3]));
        }
        mx0 = fmaxf(mx0, __shfl_xor_sync(0xffffffffu, mx0, 1));
        mx0 = fmaxf(mx0, __shfl_xor_sync(0xffffffffu, mx0, 2));
        mx1 = fmaxf(mx1, __shfl_xor_sync(0xffffffffu, mx1, 1));
        mx1 = fmaxf(mx1, __shfl_xor_sync(0xffffffffu, mx1, 2));
        const float mn0 = fmaxf(m0, mx0), mn1 = fmaxf(m1, mx1);
        const float c0 = __expf(m0 - mn0), c1 = __expf(m1 - mn1);
        m0 = mn0; m1 = mn1;
        float sum0 = 0.f, sum1 = 0.f;
#pragma unroll
        for (int g = 0; g < 8; g++) {
            s[g][0] = __expf(s[g][0] - mn0);
            s[g][1] = __expf(s[g][1] - mn0);
            s[g][2] = __expf(s[g][2] - mn1);
            s[g][3] = __expf(s[g][3] - mn1);
            sum0 += s[g][0] + s[g][1];
            sum1 += s[g][2] + s[g][3];
        }
        sum0 += __shfl_xor_sync(0xffffffffu, sum0, 1);
        sum0 += __shfl_xor_sync(0xffffffffu, sum0, 2);
        sum1 += __shfl_xor_sync(0xffffffffu, sum1, 1);
        sum1 += __shfl_xor_sync(0xffffffffu, sum1, 2);
        l0 = l0 * c0 + sum0;
        l1 = l1 * c1 + sum1;
#pragma unroll
        for (int g = 0; g < 8; g++) {
            o[g][0] *= c0; o[g][1] *= c0;
            o[g][2] *= c1; o[g][3] *= c1;
        }

        // ---- P (tf32 bits) -> per-warp smem, C-frag to A-frag relayout ----
#pragma unroll
        for (int g = 0; g < 8; g++) {
            const int cc = (g * 8 + 2 * lr) ^ swn;
            uint2 p0; p0.x = f2tf32(s[g][0]); p0.y = f2tf32(s[g][1]);
            uint2 p1; p1.x = f2tf32(s[g][2]); p1.y = f2tf32(s[g][3]);
            *(uint2*)(Pw + lq * 64 + cc) = p0;
            *(uint2*)(Pw + (lq + 8) * 64 + cc) = p1;
        }
        __syncwarp();

        // ---- O += P V ----
#pragma unroll
        for (int kj = 0; kj < 8; kj++) {
            const int kc = kj * 8 + lr;
            const int ai0 = lq * 64 + (kc ^ swn);
            const int ai2 = lq * 64 + ((kc + 4) ^ swn);
            uint32_t a0 = Pw[ai0];
            uint32_t a1 = Pw[ai0 + 8 * 64];
            uint32_t a2 = Pw[ai2];
            uint32_t a3 = Pw[ai2 + 8 * 64];
            const int vr0 = kc * 64, vr1 = (kc + 4) * 64;
#pragma unroll
            for (int g = 0; g < 8; g++) {
                const int n = g * 8 + lq;
                uint32_t b0 = __float_as_uint(vs_[vr0 + (n ^ swv)]);
                uint32_t b1 = __float_as_uint(vs_[vr1 + (n ^ swv)]);
                MMA_TF32(o[g][0], o[g][1], o[g][2], o[g][3],
                         a0, a1, a2, a3, b0, b1);
            }
        }
        __syncwarp();
    }

    // ---- epilogue ----
    const float inv0 = 1.f / l0, inv1 = 1.f / l1;
    float* o0 = O + base + (size_t)(qw + lq) * D_MODEL;
    float* o1 = o0 + 8 * D_MODEL;
#pragma unroll
    for (int g = 0; g < 8; g++) {
        const int c = g * 8 + 2 * lr;
        float2 r0; r0.x = o[g][0] * inv0; r0.y = o[g][1] * inv0;
        float2 r1; r1.x = o[g][2] * inv1; r1.y = o[g][3] * inv1;
        *(float2*)(o0 + c) = r0;
        *(float2*)(o1 + c) = r1;
    }
}

// ---------------------------------------------------------------------------
extern "C" void kernel_launch(void* const* d_in, const int* in_sizes, int n_in,
                              void* d_out, int out_size)
{
    const float* x   = (const float*)d_in[0];
    const float* pos = (const float*)d_in[1];
    const float* Wq  = (const float*)d_in[2];
    const float* bq  = (const float*)d_in[3];
    const float* Wk  = (const float*)d_in[4];
    const float* bk  = (const float*)d_in[5];
    const float* Wv  = (const float*)d_in[6];
    const float* bv  = (const float*)d_in[7];
    const float* Wp  = (const float*)d_in[8];
    const float* bp  = (const float*)d_in[9];
    const float* Wo  = (const float*)d_in[10];
    const float* bo  = (const float*)d_in[11];
    float* out = (float*)d_out;

    float *q, *k, *v, *ctx, *p;
    cudaGetSymbolAddress((void**)&q,   g_q);
    cudaGetSymbolAddress((void**)&k,   g_k);
    cudaGetSymbolAddress((void**)&v,   g_v);
    cudaGetSymbolAddress((void**)&ctx, g_ctx);
    cudaGetSymbolAddress((void**)&p,   g_p);

    static bool attr_done = false;
    if (!attr_done) {
        cudaFuncSetAttribute(gemm_mma_kernel,
                             cudaFuncAttributeMaxDynamicSharedMemorySize, SM_TOTAL);
        cudaFuncSetAttribute(flash_mma_kernel,
                             cudaFuncAttributeMaxDynamicSharedMemorySize, ATT_SMEM);
        attr_done = true;
    }

    dim3 blk(256);
    dim3 gP(D_MODEL / BN, SEQ / BM);    // (8, 16)
    dim3 gX(D_MODEL / BN, NTOK / BM);   // (8, 64)

    gemm_mma_kernel<<<gP, blk, SM_TOTAL>>>(pos, Wp, bp, nullptr, p, 0, 0);
    gemm_mma_kernel<<<gX, blk, SM_TOTAL>>>(x, Wq, bq, p, q, 1, 1);
    gemm_mma_kernel<<<gX, blk, SM_TOTAL>>>(x, Wk, bk, nullptr, k, 0, 1);
    gemm_mma_kernel<<<gX, blk, SM_TOTAL>>>(x, Wv, bv, nullptr, v, 0, 1);
    flash_mma_kernel<<<dim3(SEQ / BQ, BATCH * 16), 256, ATT_SMEM>>>(q, k, v, ctx);
    gemm_mma_kernel<<<gX, blk, SM_TOTAL>>>(ctx, Wo, bo, nullptr, out, 0, 0);
}

// round 6
// speedup vs baseline: 3.5780x; 1.0097x over previous
#include <cuda_runtime.h>
#include <cstdint>
#include <math.h>

#define D_MODEL 1024
#define SEQ     2048
#define BATCH   4
#define NTOK    (BATCH * SEQ)   /* 8192 */

// ---------------- scratch (device globals; no allocations allowed) ----------
__device__ float g_q[NTOK * D_MODEL];
__device__ float g_k[NTOK * D_MODEL];
__device__ float g_v[NTOK * D_MODEL];
__device__ float g_ctx[NTOK * D_MODEL];
__device__ float g_p[SEQ * D_MODEL];
__device__ float g_x[NTOK * D_MODEL];           // tf32-rounded x
__device__ float g_pos[SEQ * D_MODEL];          // tf32-rounded pos_emb
__device__ float g_w[5][D_MODEL * D_MODEL];     // tf32-rounded Wq,Wk,Wv,Wo,Wp

// ============================ helpers =======================================
#define CP_ASYNC16(dst, src) \
    asm volatile("cp.async.cg.shared.global [%0], [%1], 16;" \
                 :: "r"(dst), "l"(src) : "memory")
#define CP_COMMIT() asm volatile("cp.async.commit_group;" ::: "memory")
#define CP_WAIT(n)  asm volatile("cp.async.wait_group %0;" :: "n"(n) : "memory")

#define SW128(off) ((off) ^ (((off) >> 3) & 0x70))

__device__ __forceinline__ uint32_t smem_u32(const void* p) {
    uint32_t a;
    asm("{ .reg .u64 t; cvta.to.shared.u64 t, %1; cvt.u32.u64 %0, t; }"
        : "=r"(a) : "l"(p));
    return a;
}

__device__ __forceinline__ uint32_t f2tf32(float f) {
    uint32_t r;
    asm("cvt.rna.tf32.f32 %0, %1;" : "=r"(r) : "f"(f));
    return r;
}

#define MMA_TF32(c0, c1, c2, c3, a0, a1, a2, a3, b0, b1) \
    asm volatile( \
        "mma.sync.aligned.m16n8k8.row.col.f32.tf32.tf32.f32 " \
        "{%0,%1,%2,%3}, {%4,%5,%6,%7}, {%8,%9}, {%0,%1,%2,%3};" \
        : "+f"(c0), "+f"(c1), "+f"(c2), "+f"(c3) \
        : "r"(a0), "r"(a1), "r"(a2), "r"(a3), "r"(b0), "r"(b1))

// ---------------- tf32 pre-round (elementwise, float4 grid-stride) ----------
__global__ __launch_bounds__(256) void round_tf32_kernel(
    const float* __restrict__ src, float* __restrict__ dst, int n4)
{
    int i = blockIdx.x * blockDim.x + threadIdx.x;
    int stride = gridDim.x * blockDim.x;
    for (; i < n4; i += stride) {
        float4 t = ((const float4*)src)[i];
        t.x = __uint_as_float(f2tf32(t.x));
        t.y = __uint_as_float(f2tf32(t.y));
        t.z = __uint_as_float(f2tf32(t.z));
        t.w = __uint_as_float(f2tf32(t.w));
        ((float4*)dst)[i] = t;
    }
}

// ============================ mma.sync tf32 GEMM ============================
// Y[m,n] = sum_k X[m,k]*W[n,k] + bias[n] (+ P[m mod SEQ, n] if addP)
// Inputs X, W PRE-ROUNDED to tf32 (raw bits fed to MMA; no in-loop cvt).
// Tile 128x128x32, 512 threads (16 warps, 4x4), warp tile 32x32.
#define BM 128
#define BN 128
#define BK 32
#define GSTAGES 4
#define NCHUNK (D_MODEL / BK)      /* 32 */
#define TILE_B (BM * BK * 4)       /* 16384 bytes, same for A and B */
#define STG_B  (2 * TILE_B)        /* 32768 per stage */
#define SM_TOTAL (GSTAGES * STG_B) /* 131072 */

__device__ __forceinline__ uint32_t lds_swu(const char* base, int r, int c) {
    return *(const uint32_t*)(base + SW128(r * 128 + c * 4));
}

__device__ __forceinline__ void gemm_load_chunk(
    const float* __restrict__ X, const float* __restrict__ W,
    uint32_t sbase, int stage, int m0, int n0, int kof, int tid)
{
    const uint32_t abase = sbase + stage * STG_B;
    const uint32_t bbase = abase + TILE_B;
#pragma unroll
    for (int i = 0; i < 2; i++) {
        int seg = tid + (i << 9);
        int row = seg >> 3, c16 = seg & 7;
        uint32_t off = row * 128 + c16 * 16;
        CP_ASYNC16(abase + SW128(off),
                   X + (size_t)(m0 + row) * D_MODEL + kof + c16 * 4);
    }
#pragma unroll
    for (int i = 0; i < 2; i++) {
        int seg = tid + (i << 9);
        int row = seg >> 3, c16 = seg & 7;
        uint32_t off = row * 128 + c16 * 16;
        CP_ASYNC16(bbase + SW128(off),
                   W + (size_t)(n0 + row) * D_MODEL + kof + c16 * 4);
    }
}

__global__ __launch_bounds__(512, 1) void gemm_mma_kernel(
    const float* __restrict__ X, const float* __restrict__ W,
    const float* __restrict__ bias, const float* __restrict__ P,
    float* __restrict__ Y, int addP, int roundOut)
{
    extern __shared__ char smem[];
    const uint32_t sb = smem_u32(smem);
    const int tid = threadIdx.x;
    const int lane = tid & 31, wid = tid >> 5;
    const int wm = wid >> 2;          // 0..3
    const int wn = wid & 3;           // 0..3
    const int n0 = blockIdx.x * BN;
    const int m0 = blockIdx.y * BM;

    float acc[2][4][4];
#pragma unroll
    for (int f = 0; f < 2; f++)
#pragma unroll
        for (int g = 0; g < 4; g++)
#pragma unroll
            for (int e = 0; e < 4; e++) acc[f][g][e] = 0.f;

#pragma unroll
    for (int c = 0; c < GSTAGES - 1; c++) {
        gemm_load_chunk(X, W, sb, c, m0, n0, c * BK, tid);
        CP_COMMIT();
    }

    const int lq = lane >> 2;   // 0..7
    const int lr = lane & 3;    // 0..3

    for (int m = 0; m < NCHUNK; m++) {
        CP_WAIT(GSTAGES - 2);
        __syncthreads();

        const int pc = m + GSTAGES - 1;
        if (pc < NCHUNK)
            gemm_load_chunk(X, W, sb, pc & (GSTAGES - 1), m0, n0, pc * BK, tid);
        CP_COMMIT();

        const char* as = smem + (m & (GSTAGES - 1)) * STG_B;
        const char* bs = as + TILE_B;
#pragma unroll
        for (int ks = 0; ks < 4; ks++) {
            const int kc = ks * 8 + lr;
            uint32_t A[2][4];
#pragma unroll
            for (int f = 0; f < 2; f++) {
                const int r = wm * 32 + f * 16 + lq;
                A[f][0] = lds_swu(as, r,     kc);
                A[f][1] = lds_swu(as, r + 8, kc);
                A[f][2] = lds_swu(as, r,     kc + 4);
                A[f][3] = lds_swu(as, r + 8, kc + 4);
            }
            uint32_t B[4][2];
#pragma unroll
            for (int g = 0; g < 4; g++) {
                const int n = wn * 32 + g * 8 + lq;
                B[g][0] = lds_swu(bs, n, kc);
                B[g][1] = lds_swu(bs, n, kc + 4);
            }
#pragma unroll
            for (int f = 0; f < 2; f++)
#pragma unroll
                for (int g = 0; g < 4; g++)
                    MMA_TF32(acc[f][g][0], acc[f][g][1], acc[f][g][2], acc[f][g][3],
                             A[f][0], A[f][1], A[f][2], A[f][3],
                             B[g][0], B[g][1]);
        }
    }

#pragma unroll
    for (int f = 0; f < 2; f++) {
        const int r0 = m0 + wm * 32 + f * 16 + lq;
#pragma unroll
        for (int g = 0; g < 4; g++) {
            const int nc = n0 + wn * 32 + g * 8 + 2 * lr;
            float2 bz = *(const float2*)(bias + nc);
            float2 v0, v1;
            v0.x = acc[f][g][0] + bz.x; v0.y = acc[f][g][1] + bz.y;
            v1.x = acc[f][g][2] + bz.x; v1.y = acc[f][g][3] + bz.y;
            if (addP) {
                float2 p0 = *(const float2*)(P + (size_t)(r0 & (SEQ - 1)) * D_MODEL + nc);
                float2 p1 = *(const float2*)(P + (size_t)((r0 + 8) & (SEQ - 1)) * D_MODEL + nc);
                v0.x += p0.x; v0.y += p0.y;
                v1.x += p1.x; v1.y += p1.y;
            }
            if (roundOut) {
                v0.x = __uint_as_float(f2tf32(v0.x));
                v0.y = __uint_as_float(f2tf32(v0.y));
                v1.x = __uint_as_float(f2tf32(v1.x));
                v1.y = __uint_as_float(f2tf32(v1.y));
            }
            *(float2*)(Y + (size_t)r0 * D_MODEL + nc) = v0;
            *(float2*)(Y + (size_t)(r0 + 8) * D_MODEL + nc) = v1;
        }
    }
}

// ============================ mma.sync flash attention ======================
// BQ=128 (8 warps x m16), BJ=64, dk=64. Q frags in regs; K/V double-buffered
// cp.async; P relayout via per-warp smem. q/k/v pre-rounded to tf32 upstream.
// Epilogue rounds ctx to tf32 so the Wo GEMM can consume raw bits.
#define BQ 128
#define BJ 64
#define KV_F   (BJ * 64)                 /* 4096 floats / stage */
#define AV_OFF (2 * KV_F)                /* V stages after K stages */
#define AP_OFF (4 * KV_F)                /* P after V */
#define ATT_SMEM ((4 * KV_F + 8 * 16 * 64) * 4)  /* 98304 B */

__global__ __launch_bounds__(256, 1) void flash_mma_kernel(
    const float* __restrict__ Q, const float* __restrict__ K,
    const float* __restrict__ V, float* __restrict__ O)
{
    extern __shared__ char smem[];
    float* smf = (float*)smem;
    const int tid = threadIdx.x;
    const int lane = tid & 31, w = tid >> 5;
    const int lq = lane >> 2, lr = lane & 3;
    const int qt = gridDim.x - 1 - blockIdx.x;   // heavy tiles first
    const int bh = blockIdx.y;
    const int b = bh >> 4, h = bh & 15;
    const int q0 = qt * BQ;
    const size_t base = ((size_t)b * SEQ) * D_MODEL + h * 64;
    const uint32_t sb = smem_u32(smem);

    uint32_t* Pw = (uint32_t*)(smf + AP_OFF + w * (16 * 64));
    const int swn = lq << 2;      // K/P swizzle amount (row&7 == lq)
    const int swv = lr << 3;      // V swizzle amount ((kc&3) == lr)

    // Q fragments (tf32-rounded in gmem; *0.125 is exact)
    uint32_t qa[8][4];
    {
        const float* q0p = Q + base + (size_t)(q0 + w * 16 + lq) * D_MODEL;
        const float* q1p = q0p + 8 * D_MODEL;
#pragma unroll
        for (int ks = 0; ks < 8; ks++) {
            const int c = ks * 8 + lr;
            qa[ks][0] = __float_as_uint(q0p[c] * 0.125f);
            qa[ks][1] = __float_as_uint(q1p[c] * 0.125f);
            qa[ks][2] = __float_as_uint(q0p[c + 4] * 0.125f);
            qa[ks][3] = __float_as_uint(q1p[c + 4] * 0.125f);
        }
    }

    float o[8][4];
#pragma unroll
    for (int g = 0; g < 8; g++)
#pragma unroll
        for (int e = 0; e < 4; e++) o[g][e] = 0.f;
    float m0 = -1e30f, m1 = -1e30f, l0 = 0.f, l1 = 0.f;

    const int nj = qt * 2 + 2;

#define LOAD_KV(t_) do {                                                      \
    const int s_ = (t_) & 1;                                                  \
    const float* kg = K + base + (size_t)((t_) * BJ) * D_MODEL;               \
    const float* vg = V + base + (size_t)((t_) * BJ) * D_MODEL;               \
    const uint32_t kb = sb + s_ * (KV_F * 4);                                 \
    const uint32_t vb = sb + (AV_OFF + s_ * KV_F) * 4;                        \
    _Pragma("unroll")                                                         \
    for (int i_ = 0; i_ < 4; i_++) {                                          \
        int seg = tid + (i_ << 8);                                            \
        int row = seg >> 4, c4 = seg & 15;                                    \
        uint32_t kfi = row * 64 + ((c4 * 4) ^ ((row & 7) << 2));              \
        uint32_t vfi = row * 64 + ((c4 * 4) ^ ((row & 3) << 3));              \
        CP_ASYNC16(kb + kfi * 4, kg + (size_t)row * D_MODEL + c4 * 4);        \
        CP_ASYNC16(vb + vfi * 4, vg + (size_t)row * D_MODEL + c4 * 4);        \
    }                                                                         \
} while (0)

    LOAD_KV(0);
    CP_COMMIT();

    const int qw = q0 + w * 16;
    const int qmax = qw + 15;

    for (int t = 0; t < nj; t++) {
        CP_WAIT(0);
        __syncthreads();
        if (t + 1 < nj) { LOAD_KV(t + 1); CP_COMMIT(); }

        const float* ks_ = smf + (t & 1) * KV_F;
        const float* vs_ = smf + AV_OFF + (t & 1) * KV_F;
        const int j0 = t * BJ;

        float s[8][4];
        unsigned act = 0;
#pragma unroll
        for (int g = 0; g < 8; g++) {
            bool a = (j0 + g * 8) <= qmax;
            if (a) act |= 1u << g;
            float init = a ? 0.f : -1e30f;
            s[g][0] = init; s[g][1] = init; s[g][2] = init; s[g][3] = init;
        }
#pragma unroll
        for (int ks = 0; ks < 8; ks++) {
            const int kc = ks * 8 + lr;
#pragma unroll
            for (int g = 0; g < 8; g++) {
                if (!((act >> g) & 1)) continue;
                const int nrow = (g * 8 + lq) * 64;
                uint32_t b0 = __float_as_uint(ks_[nrow + (kc ^ swn)]);
                uint32_t b1 = __float_as_uint(ks_[nrow + ((kc + 4) ^ swn)]);
                MMA_TF32(s[g][0], s[g][1], s[g][2], s[g][3],
                         qa[ks][0], qa[ks][1], qa[ks][2], qa[ks][3], b0, b1);
            }
        }

        if (j0 + BJ - 1 > qw) {
            const int Q0 = qw + lq, Q1 = Q0 + 8;
#pragma unroll
            for (int g = 0; g < 8; g++) {
                const int jc = j0 + g * 8 + 2 * lr;
                if (jc     > Q0) s[g][0] = -1e30f;
                if (jc + 1 > Q0) s[g][1] = -1e30f;
                if (jc     > Q1) s[g][2] = -1e30f;
                if (jc + 1 > Q1) s[g][3] = -1e30f;
            }
        }

        float mx0 = -1e30f, mx1 = -1e30f;
#pragma unroll
        for (int g = 0; g < 8; g++) {
            mx0 = fmaxf(mx0, fmaxf(s[g][0], s[g][1]));
            mx1 = fmaxf(mx1, fmaxf(s[g][2], s[g][3]));
        }
        mx0 = fmaxf(mx0, __shfl_xor_sync(0xffffffffu, mx0, 1));
        mx0 = fmaxf(mx0, __shfl_xor_sync(0xffffffffu, mx0, 2));
        mx1 = fmaxf(mx1, __shfl_xor_sync(0xffffffffu, mx1, 1));
        mx1 = fmaxf(mx1, __shfl_xor_sync(0xffffffffu, mx1, 2));
        const float mn0 = fmaxf(m0, mx0), mn1 = fmaxf(m1, mx1);
        const float c0 = __expf(m0 - mn0), c1 = __expf(m1 - mn1);
        m0 = mn0; m1 = mn1;
        float sum0 = 0.f, sum1 = 0.f;
#pragma unroll
        for (int g = 0; g < 8; g++) {
            s[g][0] = __expf(s[g][0] - mn0);
            s[g][1] = __expf(s[g][1] - mn0);
            s[g][2] = __expf(s[g][2] - mn1);
            s[g][3] = __expf(s[g][3] - mn1);
            sum0 += s[g][0] + s[g][1];
            sum1 += s[g][2] + s[g][3];
        }
        sum0 += __shfl_xor_sync(0xffffffffu, sum0, 1);
        sum0 += __shfl_xor_sync(0xffffffffu, sum0, 2);
        sum1 += __shfl_xor_sync(0xffffffffu, sum1, 1);
        sum1 += __shfl_xor_sync(0xffffffffu, sum1, 2);
        l0 = l0 * c0 + sum0;
        l1 = l1 * c1 + sum1;
#pragma unroll
        for (int g = 0; g < 8; g++) {
            o[g][0] *= c0; o[g][1] *= c0;
            o[g][2] *= c1; o[g][3] *= c1;
        }

#pragma unroll
        for (int g = 0; g < 8; g++) {
            const int cc = (g * 8 + 2 * lr) ^ swn;
            uint2 p0; p0.x = f2tf32(s[g][0]); p0.y = f2tf32(s[g][1]);
            uint2 p1; p1.x = f2tf32(s[g][2]); p1.y = f2tf32(s[g][3]);
            *(uint2*)(Pw + lq * 64 + cc) = p0;
            *(uint2*)(Pw + (lq + 8) * 64 + cc) = p1;
        }
        __syncwarp();

#pragma unroll
        for (int kj = 0; kj < 8; kj++) {
            const int kc = kj * 8 + lr;
            const int ai0 = lq * 64 + (kc ^ swn);
            const int ai2 = lq * 64 + ((kc + 4) ^ swn);
            uint32_t a0 = Pw[ai0];
            uint32_t a1 = Pw[ai0 + 8 * 64];
            uint32_t a2 = Pw[ai2];
            uint32_t a3 = Pw[ai2 + 8 * 64];
            const int vr0 = kc * 64, vr1 = (kc + 4) * 64;
#pragma unroll
            for (int g = 0; g < 8; g++) {
                const int n = g * 8 + lq;
                uint32_t b0 = __float_as_uint(vs_[vr0 + (n ^ swv)]);
                uint32_t b1 = __float_as_uint(vs_[vr1 + (n ^ swv)]);
                MMA_TF32(o[g][0], o[g][1], o[g][2], o[g][3],
                         a0, a1, a2, a3, b0, b1);
            }
        }
        __syncwarp();
    }

    // epilogue: normalize + round to tf32 (Wo GEMM consumes raw bits)
    const float inv0 = 1.f / l0, inv1 = 1.f / l1;
    float* o0 = O + base + (size_t)(qw + lq) * D_MODEL;
    float* o1 = o0 + 8 * D_MODEL;
#pragma unroll
    for (int g = 0; g < 8; g++) {
        const int c = g * 8 + 2 * lr;
        float2 r0, r1;
        r0.x = __uint_as_float(f2tf32(o[g][0] * inv0));
        r0.y = __uint_as_float(f2tf32(o[g][1] * inv0));
        r1.x = __uint_as_float(f2tf32(o[g][2] * inv1));
        r1.y = __uint_as_float(f2tf32(o[g][3] * inv1));
        *(float2*)(o0 + c) = r0;
        *(float2*)(o1 + c) = r1;
    }
}

// ---------------------------------------------------------------------------
extern "C" void kernel_launch(void* const* d_in, const int* in_sizes, int n_in,
                              void* d_out, int out_size)
{
    const float* x   = (const float*)d_in[0];
    const float* pos = (const float*)d_in[1];
    const float* Wq  = (const float*)d_in[2];
    const float* bq  = (const float*)d_in[3];
    const float* Wk  = (const float*)d_in[4];
    const float* bk  = (const float*)d_in[5];
    const float* Wv  = (const float*)d_in[6];
    const float* bv  = (const float*)d_in[7];
    const float* Wp  = (const float*)d_in[8];
    const float* bp  = (const float*)d_in[9];
    const float* Wo  = (const float*)d_in[10];
    const float* bo  = (const float*)d_in[11];
    float* out = (float*)d_out;

    float *q, *k, *v, *ctx, *p, *xr, *posr, *wr;
    cudaGetSymbolAddress((void**)&q,    g_q);
    cudaGetSymbolAddress((void**)&k,    g_k);
    cudaGetSymbolAddress((void**)&v,    g_v);
    cudaGetSymbolAddress((void**)&ctx,  g_ctx);
    cudaGetSymbolAddress((void**)&p,    g_p);
    cudaGetSymbolAddress((void**)&xr,   g_x);
    cudaGetSymbolAddress((void**)&posr, g_pos);
    cudaGetSymbolAddress((void**)&wr,   g_w);

    float* wq_r = wr + 0 * (size_t)D_MODEL * D_MODEL;
    float* wk_r = wr + 1 * (size_t)D_MODEL * D_MODEL;
    float* wv_r = wr + 2 * (size_t)D_MODEL * D_MODEL;
    float* wo_r = wr + 3 * (size_t)D_MODEL * D_MODEL;
    float* wp_r = wr + 4 * (size_t)D_MODEL * D_MODEL;

    static bool attr_done = false;
    if (!attr_done) {
        cudaFuncSetAttribute(gemm_mma_kernel,
                             cudaFuncAttributeMaxDynamicSharedMemorySize, SM_TOTAL);
        cudaFuncSetAttribute(flash_mma_kernel,
                             cudaFuncAttributeMaxDynamicSharedMemorySize, ATT_SMEM);
        attr_done = true;
    }

    // ---- tf32 pre-round of all MMA inputs ----
    const int W4 = D_MODEL * D_MODEL / 4;
    round_tf32_kernel<<<592, 256>>>(x,   xr,   NTOK * D_MODEL / 4);
    round_tf32_kernel<<<592, 256>>>(pos, posr, SEQ * D_MODEL / 4);
    round_tf32_kernel<<<296, 256>>>(Wq, wq_r, W4);
    round_tf32_kernel<<<296, 256>>>(Wk, wk_r, W4);
    round_tf32_kernel<<<296, 256>>>(Wv, wv_r, W4);
    round_tf32_kernel<<<296, 256>>>(Wo, wo_r, W4);
    round_tf32_kernel<<<296, 256>>>(Wp, wp_r, W4);

    dim3 blk(512);
    dim3 gP(D_MODEL / BN, SEQ / BM);    // (8, 16)
    dim3 gX(D_MODEL / BN, NTOK / BM);   // (8, 64)

    gemm_mma_kernel<<<gP, blk, SM_TOTAL>>>(posr, wp_r, bp, nullptr, p, 0, 0);
    gemm_mma_kernel<<<gX, blk, SM_TOTAL>>>(xr, wq_r, bq, p, q, 1, 1);
    gemm_mma_kernel<<<gX, blk, SM_TOTAL>>>(xr, wk_r, bk, nullptr, k, 0, 1);
    gemm_mma_kernel<<<gX, blk, SM_TOTAL>>>(xr, wv_r, bv, nullptr, v, 0, 1);
    flash_mma_kernel<<<dim3(SEQ / BQ, BATCH * 16), 256, ATT_SMEM>>>(q, k, v, ctx);
    gemm_mma_kernel<<<gX, blk, SM_TOTAL>>>(ctx, wo_r, bo, nullptr, out, 0, 0);
}

// round 7
// speedup vs baseline: 6.1892x; 1.7298x over previous
#include <cuda_runtime.h>
#include <cuda_fp16.h>
#include <cstdint>
#include <math.h>

#define D_MODEL 1024
#define SEQ     2048
#define BATCH   4
#define NTOK    (BATCH * SEQ)   /* 8192 */

// ---------------- scratch (device globals; no allocations allowed) ----------
__device__ __half g_xh[NTOK * D_MODEL];
__device__ __half g_posh[SEQ * D_MODEL];
__device__ __half g_wh[5][D_MODEL * D_MODEL];   // Wq,Wk,Wv,Wo,Wp (fp16)
__device__ __half g_qh[NTOK * D_MODEL];
__device__ __half g_kh[NTOK * D_MODEL];
__device__ __half g_vh[NTOK * D_MODEL];
__device__ __half g_ctxh[NTOK * D_MODEL];
__device__ float  g_p[SEQ * D_MODEL];           // pos projection (fp32)

// ============================ helpers =======================================
#define CP_ASYNC16(dst, src) \
    asm volatile("cp.async.cg.shared.global [%0], [%1], 16;" \
                 :: "r"(dst), "l"(src) : "memory")
#define CP_COMMIT() asm volatile("cp.async.commit_group;" ::: "memory")
#define CP_WAIT(n)  asm volatile("cp.async.wait_group %0;" :: "n"(n) : "memory")

#define SW128(off) ((off) ^ (((off) >> 3) & 0x70))

__device__ __forceinline__ uint32_t smem_u32(const void* p) {
    uint32_t a;
    asm("{ .reg .u64 t; cvta.to.shared.u64 t, %1; cvt.u32.u64 %0, t; }"
        : "=r"(a) : "l"(p));
    return a;
}

__device__ __forceinline__ uint32_t pack_half2(float a, float b) {
    __half2 h = __floats2half2_rn(a, b);
    return *(uint32_t*)&h;
}

#define LDSM4(r0, r1, r2, r3, addr) \
    asm volatile("ldmatrix.sync.aligned.m8n8.x4.shared.b16 {%0,%1,%2,%3}, [%4];" \
                 : "=r"(r0), "=r"(r1), "=r"(r2), "=r"(r3) : "r"(addr))

#define LDSM4T(r0, r1, r2, r3, addr) \
    asm volatile("ldmatrix.sync.aligned.m8n8.x4.trans.shared.b16 {%0,%1,%2,%3}, [%4];" \
                 : "=r"(r0), "=r"(r1), "=r"(r2), "=r"(r3) : "r"(addr))

#define MMA_F16(c, a0, a1, a2, a3, b0, b1) \
    asm volatile( \
        "mma.sync.aligned.m16n8k16.row.col.f32.f16.f16.f32 " \
        "{%0,%1,%2,%3}, {%4,%5,%6,%7}, {%8,%9}, {%0,%1,%2,%3};" \
        : "+f"((c)[0]), "+f"((c)[1]), "+f"((c)[2]), "+f"((c)[3]) \
        : "r"(a0), "r"(a1), "r"(a2), "r"(a3), "r"(b0), "r"(b1))

// ---------------- fp32 -> fp16 pack (float4 grid-stride) --------------------
__global__ __launch_bounds__(256) void pack_half_kernel(
    const float* __restrict__ src, __half* __restrict__ dst, int n4)
{
    int i = blockIdx.x * blockDim.x + threadIdx.x;
    int stride = gridDim.x * blockDim.x;
    for (; i < n4; i += stride) {
        float4 t = ((const float4*)src)[i];
        uint2 r;
        r.x = pack_half2(t.x, t.y);
        r.y = pack_half2(t.z, t.w);
        ((uint2*)dst)[i] = r;
    }
}

// ============================ fp16 mma GEMM =================================
// Y[m,n] = sum_k X[m,k]*W[n,k] + bias[n] (+ P[m mod SEQ, n] if addP)
// X, W fp16; accumulate fp32; output fp16 (halfOut) or fp32.
// Tile 128x128x64(half), 512 threads (16 warps 4x4), warp tile 32x32.
// ldmatrix.x4 fragment loads from SW128-swizzled smem (128B rows).
#define BM 128
#define BN 128
#define BKH 64                      /* k-halves per chunk (128 bytes) */
#define GSTAGES 4
#define NCHUNK (D_MODEL / BKH)      /* 16 */
#define TILE_B (BM * BKH * 2)       /* 16384 B */
#define STG_B  (2 * TILE_B)         /* 32768 B */
#define SM_TOTAL (GSTAGES * STG_B)  /* 131072 B */

__device__ __forceinline__ void gemm_load_chunk(
    const __half* __restrict__ X, const __half* __restrict__ W,
    uint32_t sbase, int stage, int m0, int n0, int kof, int tid)
{
    const uint32_t abase = sbase + stage * STG_B;
    const uint32_t bbase = abase + TILE_B;
#pragma unroll
    for (int i = 0; i < 2; i++) {
        int seg = tid + (i << 9);
        int row = seg >> 3, c16 = seg & 7;
        uint32_t off = row * 128 + c16 * 16;
        CP_ASYNC16(abase + SW128(off),
                   X + (size_t)(m0 + row) * D_MODEL + kof + c16 * 8);
    }
#pragma unroll
    for (int i = 0; i < 2; i++) {
        int seg = tid + (i << 9);
        int row = seg >> 3, c16 = seg & 7;
        uint32_t off = row * 128 + c16 * 16;
        CP_ASYNC16(bbase + SW128(off),
                   W + (size_t)(n0 + row) * D_MODEL + kof + c16 * 8);
    }
}

__global__ __launch_bounds__(512, 1) void gemm_f16_kernel(
    const __half* __restrict__ X, const __half* __restrict__ W,
    const float* __restrict__ bias, const float* __restrict__ P,
    void* __restrict__ Yv, int addP, int halfOut)
{
    extern __shared__ char smem[];
    const uint32_t sb = smem_u32(smem);
    const int tid = threadIdx.x;
    const int lane = tid & 31, wid = tid >> 5;
    const int wm = wid >> 2;          // 0..3
    const int wn = wid & 3;           // 0..3
    const int grp = lane >> 3, lrow = lane & 7;
    const int lq = lane >> 2, lr = lane & 3;
    const int n0 = blockIdx.x * BN;
    const int m0 = blockIdx.y * BM;

    float acc[2][4][4];
#pragma unroll
    for (int f = 0; f < 2; f++)
#pragma unroll
        for (int g = 0; g < 4; g++)
#pragma unroll
            for (int e = 0; e < 4; e++) acc[f][g][e] = 0.f;

#pragma unroll
    for (int c = 0; c < GSTAGES - 1; c++) {
        gemm_load_chunk(X, W, sb, c, m0, n0, c * BKH, tid);
        CP_COMMIT();
    }

    for (int m = 0; m < NCHUNK; m++) {
        CP_WAIT(GSTAGES - 2);
        __syncthreads();

        const int pc = m + GSTAGES - 1;
        if (pc < NCHUNK)
            gemm_load_chunk(X, W, sb, pc & (GSTAGES - 1), m0, n0, pc * BKH, tid);
        CP_COMMIT();

        const uint32_t abase = sb + (m & (GSTAGES - 1)) * STG_B;
        const uint32_t bbase = abase + TILE_B;
#pragma unroll
        for (int ks = 0; ks < 4; ks++) {
            const int kc = ks * 16;
            uint32_t A[2][4], B[2][4];
#pragma unroll
            for (int f = 0; f < 2; f++) {
                const int r = wm * 32 + f * 16 + lrow + (grp & 1) * 8;
                const int c = kc + (grp >> 1) * 8;
                LDSM4(A[f][0], A[f][1], A[f][2], A[f][3],
                      abase + SW128((uint32_t)(r * 128 + c * 2)));
            }
#pragma unroll
            for (int u = 0; u < 2; u++) {
                const int r = wn * 32 + u * 16 + lrow + (grp >> 1) * 8;
                const int c = kc + (grp & 1) * 8;
                LDSM4(B[u][0], B[u][1], B[u][2], B[u][3],
                      bbase + SW128((uint32_t)(r * 128 + c * 2)));
            }
#pragma unroll
            for (int f = 0; f < 2; f++)
#pragma unroll
                for (int u = 0; u < 2; u++) {
                    MMA_F16(acc[f][2 * u],     A[f][0], A[f][1], A[f][2], A[f][3],
                            B[u][0], B[u][1]);
                    MMA_F16(acc[f][2 * u + 1], A[f][0], A[f][1], A[f][2], A[f][3],
                            B[u][2], B[u][3]);
                }
        }
    }

    __half* Yh = (__half*)Yv;
    float*  Yf = (float*)Yv;
#pragma unroll
    for (int f = 0; f < 2; f++) {
        const int r0 = m0 + wm * 32 + f * 16 + lq;
#pragma unroll
        for (int g = 0; g < 4; g++) {
            const int nc = n0 + wn * 32 + g * 8 + 2 * lr;
            float2 bz = *(const float2*)(bias + nc);
            float2 v0, v1;
            v0.x = acc[f][g][0] + bz.x; v0.y = acc[f][g][1] + bz.y;
            v1.x = acc[f][g][2] + bz.x; v1.y = acc[f][g][3] + bz.y;
            if (addP) {
                float2 p0 = *(const float2*)(P + (size_t)(r0 & (SEQ - 1)) * D_MODEL + nc);
                float2 p1 = *(const float2*)(P + (size_t)((r0 + 8) & (SEQ - 1)) * D_MODEL + nc);
                v0.x += p0.x; v0.y += p0.y;
                v1.x += p1.x; v1.y += p1.y;
            }
            if (halfOut) {
                *(uint32_t*)(Yh + (size_t)r0 * D_MODEL + nc) = pack_half2(v0.x, v0.y);
                *(uint32_t*)(Yh + (size_t)(r0 + 8) * D_MODEL + nc) = pack_half2(v1.x, v1.y);
            } else {
                *(float2*)(Yf + (size_t)r0 * D_MODEL + nc) = v0;
                *(float2*)(Yf + (size_t)(r0 + 8) * D_MODEL + nc) = v1;
            }
        }
    }
}

// ============================ fp16 flash attention ==========================
// BQ=128 (8 warps x m16), BJ=64, dk=64. Q frags in regs; K/V double-buffered
// cp.async, SW128 rows, ldmatrix (V via .trans). P stays in registers:
// the S C-fragment converts directly into the PV A-fragment.
#define BQ 128
#define BJ 64
#define KTILE_B (BJ * 64 * 2)            /* 8192 B per stage */
#define AVB_OFF (2 * KTILE_B)            /* V after 2 K stages */
#define ATT_SMEM (4 * KTILE_B)           /* 32768 B */

__global__ __launch_bounds__(256, 1) void flash_f16_kernel(
    const __half* __restrict__ Q, const __half* __restrict__ K,
    const __half* __restrict__ V, __half* __restrict__ O)
{
    extern __shared__ char smem[];
    const uint32_t sb = smem_u32(smem);
    const int tid = threadIdx.x;
    const int lane = tid & 31, w = tid >> 5;
    const int lq = lane >> 2, lr = lane & 3;
    const int grp = lane >> 3, lrow = lane & 7;
    const int qt = gridDim.x - 1 - blockIdx.x;   // heavy tiles first
    const int bh = blockIdx.y;
    const int b = bh >> 4, h = bh & 15;
    const int q0 = qt * BQ;
    const size_t base = ((size_t)b * SEQ) * D_MODEL + h * 64;

    // Q fragments: qa[ks][0..3] for k16 steps ks=0..3
    uint32_t qa[4][4];
    {
        const __half* q0p = Q + base + (size_t)(q0 + w * 16 + lq) * D_MODEL;
        const __half* q1p = q0p + 8 * D_MODEL;
#pragma unroll
        for (int ks = 0; ks < 4; ks++) {
            const int c = ks * 16 + 2 * lr;
            qa[ks][0] = *(const uint32_t*)(q0p + c);
            qa[ks][1] = *(const uint32_t*)(q1p + c);
            qa[ks][2] = *(const uint32_t*)(q0p + c + 8);
            qa[ks][3] = *(const uint32_t*)(q1p + c + 8);
        }
    }

    float o[8][4];
#pragma unroll
    for (int g = 0; g < 8; g++)
#pragma unroll
        for (int e = 0; e < 4; e++) o[g][e] = 0.f;
    float m0 = -1e30f, m1 = -1e30f, l0 = 0.f, l1 = 0.f;

    const int nj = qt * 2 + 2;

#define LOAD_KV(t_) do {                                                      \
    const int s_ = (t_) & 1;                                                  \
    const __half* kg = K + base + (size_t)((t_) * BJ) * D_MODEL;              \
    const __half* vg = V + base + (size_t)((t_) * BJ) * D_MODEL;              \
    const uint32_t kb = sb + s_ * KTILE_B;                                    \
    const uint32_t vb = sb + AVB_OFF + s_ * KTILE_B;                          \
    _Pragma("unroll")                                                         \
    for (int i_ = 0; i_ < 4; i_++) {                                          \
        int seg = tid + (i_ << 8);          /* 0..1023 */                     \
        int kv = seg >> 9;                  /* 0=K, 1=V */                    \
        int s2 = seg & 511;                                                   \
        int row = s2 >> 3, c16 = s2 & 7;                                      \
        uint32_t off = SW128((uint32_t)(row * 128 + c16 * 16));               \
        const __half* src = (kv ? vg : kg) + (size_t)row * D_MODEL + c16 * 8; \
        CP_ASYNC16((kv ? vb : kb) + off, src);                                \
    }                                                                         \
} while (0)

    LOAD_KV(0);
    CP_COMMIT();

    const int qw = q0 + w * 16;
    const int qmax = qw + 15;

    for (int t = 0; t < nj; t++) {
        CP_WAIT(0);
        __syncthreads();
        if (t + 1 < nj) { LOAD_KV(t + 1); CP_COMMIT(); }

        const uint32_t kbase = sb + (t & 1) * KTILE_B;
        const uint32_t vbase = sb + AVB_OFF + (t & 1) * KTILE_B;
        const int j0 = t * BJ;

        // ---- S = Q K^T ----
        float s[8][4];
#pragma unroll
        for (int g = 0; g < 8; g++) {
            float init = ((j0 + g * 8) <= qmax) ? 0.f : -1e30f;
            s[g][0] = init; s[g][1] = init; s[g][2] = init; s[g][3] = init;
        }
#pragma unroll
        for (int ks = 0; ks < 4; ks++) {
            const int kc = ks * 16;
#pragma unroll
            for (int u = 0; u < 4; u++) {
                if ((j0 + u * 16) > qmax) continue;     // pair fully masked
                const int r = u * 16 + lrow + (grp >> 1) * 8;
                const int c = kc + (grp & 1) * 8;
                uint32_t b0, b1, b2, b3;
                LDSM4(b0, b1, b2, b3, kbase + SW128((uint32_t)(r * 128 + c * 2)));
                MMA_F16(s[2 * u],     qa[ks][0], qa[ks][1], qa[ks][2], qa[ks][3], b0, b1);
                MMA_F16(s[2 * u + 1], qa[ks][0], qa[ks][1], qa[ks][2], qa[ks][3], b2, b3);
            }
        }

        // ---- scale + causal element mask ----
#pragma unroll
        for (int g = 0; g < 8; g++) {
            s[g][0] *= 0.125f; s[g][1] *= 0.125f;
            s[g][2] *= 0.125f; s[g][3] *= 0.125f;
        }
        if (j0 + BJ - 1 > qw) {
            const int Q0 = qw + lq, Q1 = Q0 + 8;
#pragma unroll
            for (int g = 0; g < 8; g++) {
                const int jc = j0 + g * 8 + 2 * lr;
                if (jc     > Q0) s[g][0] = -1e30f;
                if (jc + 1 > Q0) s[g][1] = -1e30f;
                if (jc     > Q1) s[g][2] = -1e30f;
                if (jc + 1 > Q1) s[g][3] = -1e30f;
            }
        }

        // ---- online softmax (rows lq / lq+8; reduce over 4 lr lanes) ----
        float mx0 = -1e30f, mx1 = -1e30f;
#pragma unroll
        for (int g = 0; g < 8; g++) {
            mx0 = fmaxf(mx0, fmaxf(s[g][0], s[g][1]));
            mx1 = fmaxf(mx1, fmaxf(s[g][2], s[g][3]));
        }
        mx0 = fmaxf(mx0, __shfl_xor_sync(0xffffffffu, mx0, 1));
        mx0 = fmaxf(mx0, __shfl_xor_sync(0xffffffffu, mx0, 2));
        mx1 = fmaxf(mx1, __shfl_xor_sync(0xffffffffu, mx1, 1));
        mx1 = fmaxf(mx1, __shfl_xor_sync(0xffffffffu, mx1, 2));
        const float mn0 = fmaxf(m0, mx0), mn1 = fmaxf(m1, mx1);
        const float c0 = __expf(m0 - mn0), c1 = __expf(m1 - mn1);
        m0 = mn0; m1 = mn1;
        float sum0 = 0.f, sum1 = 0.f;
#pragma unroll
        for (int g = 0; g < 8; g++) {
            s[g][0] = __expf(s[g][0] - mn0);
            s[g][1] = __expf(s[g][1] - mn0);
            s[g][2] = __expf(s[g][2] - mn1);
            s[g][3] = __expf(s[g][3] - mn1);
            sum0 += s[g][0] + s[g][1];
            sum1 += s[g][2] + s[g][3];
        }
        sum0 += __shfl_xor_sync(0xffffffffu, sum0, 1);
        sum0 += __shfl_xor_sync(0xffffffffu, sum0, 2);
        sum1 += __shfl_xor_sync(0xffffffffu, sum1, 1);
        sum1 += __shfl_xor_sync(0xffffffffu, sum1, 2);
        l0 = l0 * c0 + sum0;
        l1 = l1 * c1 + sum1;
#pragma unroll
        for (int g = 0; g < 8; g++) {
            o[g][0] *= c0; o[g][1] *= c0;
            o[g][2] *= c1; o[g][3] *= c1;
        }

        // ---- P: S C-frag -> PV A-frag, entirely in registers ----
        uint32_t pa[4][4];
#pragma unroll
        for (int u = 0; u < 4; u++) {
            pa[u][0] = pack_half2(s[2 * u][0],     s[2 * u][1]);
            pa[u][1] = pack_half2(s[2 * u][2],     s[2 * u][3]);
            pa[u][2] = pack_half2(s[2 * u + 1][0], s[2 * u + 1][1]);
            pa[u][3] = pack_half2(s[2 * u + 1][2], s[2 * u + 1][3]);
        }

        // ---- O += P V  (V via ldmatrix.trans: [j][d] -> B frag [d][j]) ----
#pragma unroll
        for (int kj = 0; kj < 4; kj++) {
            const int jb = kj * 16;
#pragma unroll
            for (int u = 0; u < 4; u++) {
                const int r = jb + lrow + (grp & 1) * 8;
                const int c = u * 16 + (grp >> 1) * 8;
                uint32_t b0, b1, b2, b3;
                LDSM4T(b0, b1, b2, b3, vbase + SW128((uint32_t)(r * 128 + c * 2)));
                MMA_F16(o[2 * u],     pa[kj][0], pa[kj][1], pa[kj][2], pa[kj][3], b0, b1);
                MMA_F16(o[2 * u + 1], pa[kj][0], pa[kj][1], pa[kj][2], pa[kj][3], b2, b3);
            }
        }
    }

    // ---- epilogue: normalize, store ctx as fp16 ----
    const float inv0 = 1.f / l0, inv1 = 1.f / l1;
    __half* o0 = O + base + (size_t)(qw + lq) * D_MODEL;
    __half* o1 = o0 + 8 * D_MODEL;
#pragma unroll
    for (int g = 0; g < 8; g++) {
        const int c = g * 8 + 2 * lr;
        *(uint32_t*)(o0 + c) = pack_half2(o[g][0] * inv0, o[g][1] * inv0);
        *(uint32_t*)(o1 + c) = pack_half2(o[g][2] * inv1, o[g][3] * inv1);
    }
}

// ---------------------------------------------------------------------------
extern "C" void kernel_launch(void* const* d_in, const int* in_sizes, int n_in,
                              void* d_out, int out_size)
{
    const float* x   = (const float*)d_in[0];
    const float* pos = (const float*)d_in[1];
    const float* Wq  = (const float*)d_in[2];
    const float* bq  = (const float*)d_in[3];
    const float* Wk  = (const float*)d_in[4];
    const float* bk  = (const float*)d_in[5];
    const float* Wv  = (const float*)d_in[6];
    const float* bv  = (const float*)d_in[7];
    const float* Wp  = (const float*)d_in[8];
    const float* bp  = (const float*)d_in[9];
    const float* Wo  = (const float*)d_in[10];
    const float* bo  = (const float*)d_in[11];
    float* out = (float*)d_out;

    __half *xh, *posh, *wh, *qh, *kh, *vh, *ctxh;
    float* p;
    cudaGetSymbolAddress((void**)&xh,   g_xh);
    cudaGetSymbolAddress((void**)&posh, g_posh);
    cudaGetSymbolAddress((void**)&wh,   g_wh);
    cudaGetSymbolAddress((void**)&qh,   g_qh);
    cudaGetSymbolAddress((void**)&kh,   g_kh);
    cudaGetSymbolAddress((void**)&vh,   g_vh);
    cudaGetSymbolAddress((void**)&ctxh, g_ctxh);
    cudaGetSymbolAddress((void**)&p,    g_p);

    __half* wqh = wh + 0 * (size_t)D_MODEL * D_MODEL;
    __half* wkh = wh + 1 * (size_t)D_MODEL * D_MODEL;
    __half* wvh = wh + 2 * (size_t)D_MODEL * D_MODEL;
    __half* woh = wh + 3 * (size_t)D_MODEL * D_MODEL;
    __half* wph = wh + 4 * (size_t)D_MODEL * D_MODEL;

    static bool attr_done = false;
    if (!attr_done) {
        cudaFuncSetAttribute(gemm_f16_kernel,
                             cudaFuncAttributeMaxDynamicSharedMemorySize, SM_TOTAL);
        cudaFuncSetAttribute(flash_f16_kernel,
                             cudaFuncAttributeMaxDynamicSharedMemorySize, ATT_SMEM);
        attr_done = true;
    }

    // ---- fp16 pack of all MMA inputs ----
    const int W4 = D_MODEL * D_MODEL / 4;
    pack_half_kernel<<<1184, 256>>>(x,   xh,   NTOK * D_MODEL / 4);
    pack_half_kernel<<<592, 256>>>(pos, posh, SEQ * D_MODEL / 4);
    pack_half_kernel<<<296, 256>>>(Wq, wqh, W4);
    pack_half_kernel<<<296, 256>>>(Wk, wkh, W4);
    pack_half_kernel<<<296, 256>>>(Wv, wvh, W4);
    pack_half_kernel<<<296, 256>>>(Wo, woh, W4);
    pack_half_kernel<<<296, 256>>>(Wp, wph, W4);

    dim3 blk(512);
    dim3 gP(D_MODEL / BN, SEQ / BM);    // (8, 16)
    dim3 gX(D_MODEL / BN, NTOK / BM);   // (8, 64)

    // p = pos @ Wp^T + bp (fp32 out)
    gemm_f16_kernel<<<gP, blk, SM_TOTAL>>>(posh, wph, bp, nullptr, p, 0, 0);
    // q/k/v (fp16 out; q adds p)
    gemm_f16_kernel<<<gX, blk, SM_TOTAL>>>(xh, wqh, bq, p, qh, 1, 1);
    gemm_f16_kernel<<<gX, blk, SM_TOTAL>>>(xh, wkh, bk, nullptr, kh, 0, 1);
    gemm_f16_kernel<<<gX, blk, SM_TOTAL>>>(xh, wvh, bv, nullptr, vh, 0, 1);
    // attention -> ctx (fp16)
    flash_f16_kernel<<<dim3(SEQ / BQ, BATCH * 16), 256, ATT_SMEM>>>(qh, kh, vh, ctxh);
    // out = ctx @ Wo^T + bo (fp32 out)
    gemm_f16_kernel<<<gX, blk, SM_TOTAL>>>(ctxh, woh, bo, nullptr, out, 0, 0);
}

// round 8
// speedup vs baseline: 6.6963x; 1.0819x over previous
#include <cuda_runtime.h>
#include <cuda_fp16.h>
#include <cstdint>
#include <math.h>

#define D_MODEL 1024
#define SEQ     2048
#define BATCH   4
#define NTOK    (BATCH * SEQ)   /* 8192 */

// ---------------- scratch (device globals; no allocations allowed) ----------
__device__ __half g_xh[NTOK * D_MODEL];
__device__ __half g_posh[SEQ * D_MODEL];
__device__ __half g_wh[5][D_MODEL * D_MODEL];   // Wq,Wk,Wv,Wo,Wp (fp16)
__device__ __half g_qkvh[3 * NTOK * D_MODEL];   // q, k, v contiguous
__device__ __half g_ctxh[NTOK * D_MODEL];
__device__ float  g_p[SEQ * D_MODEL];           // pos projection (fp32)
__device__ float  g_bqkv[3 * D_MODEL];          // bq|bk|bv concatenated

// ============================ helpers =======================================
#define CP_ASYNC16(dst, src) \
    asm volatile("cp.async.cg.shared.global [%0], [%1], 16;" \
                 :: "r"(dst), "l"(src) : "memory")
#define CP_COMMIT() asm volatile("cp.async.commit_group;" ::: "memory")
#define CP_WAIT(n)  asm volatile("cp.async.wait_group %0;" :: "n"(n) : "memory")

#define SW128(off) ((off) ^ (((off) >> 3) & 0x70))

__device__ __forceinline__ uint32_t smem_u32(const void* p) {
    uint32_t a;
    asm("{ .reg .u64 t; cvta.to.shared.u64 t, %1; cvt.u32.u64 %0, t; }"
        : "=r"(a) : "l"(p));
    return a;
}

__device__ __forceinline__ uint32_t pack_half2(float a, float b) {
    __half2 h = __floats2half2_rn(a, b);
    return *(uint32_t*)&h;
}

#define LDSM4(r0, r1, r2, r3, addr) \
    asm volatile("ldmatrix.sync.aligned.m8n8.x4.shared.b16 {%0,%1,%2,%3}, [%4];" \
                 : "=r"(r0), "=r"(r1), "=r"(r2), "=r"(r3) : "r"(addr))

#define LDSM4T(r0, r1, r2, r3, addr) \
    asm volatile("ldmatrix.sync.aligned.m8n8.x4.trans.shared.b16 {%0,%1,%2,%3}, [%4];" \
                 : "=r"(r0), "=r"(r1), "=r"(r2), "=r"(r3) : "r"(addr))

#define MMA_F16(c, a0, a1, a2, a3, b0, b1) \
    asm volatile( \
        "mma.sync.aligned.m16n8k16.row.col.f32.f16.f16.f32 " \
        "{%0,%1,%2,%3}, {%4,%5,%6,%7}, {%8,%9}, {%0,%1,%2,%3};" \
        : "+f"((c)[0]), "+f"((c)[1]), "+f"((c)[2]), "+f"((c)[3]) \
        : "r"(a0), "r"(a1), "r"(a2), "r"(a3), "r"(b0), "r"(b1))

// ---------------- fused pack: x, pos, 5 weights -> fp16; bq|bk|bv -> fp32 ---
#define N4_X   (NTOK * D_MODEL / 4)      /* 2097152 */
#define N4_POS (SEQ * D_MODEL / 4)       /*  524288 */
#define N4_W   (D_MODEL * D_MODEL / 4)   /*  262144 */
#define N4_TOT (N4_X + N4_POS + 5 * N4_W)

__global__ __launch_bounds__(256) void pack_all_kernel(
    const float* __restrict__ x, const float* __restrict__ pos,
    const float* __restrict__ Wq, const float* __restrict__ Wk,
    const float* __restrict__ Wv, const float* __restrict__ Wo,
    const float* __restrict__ Wp,
    const float* __restrict__ bq, const float* __restrict__ bk,
    const float* __restrict__ bv,
    __half* __restrict__ xh, __half* __restrict__ posh,
    __half* __restrict__ wh, float* __restrict__ bqkv)
{
    int i = blockIdx.x * blockDim.x + threadIdx.x;
    const int stride = gridDim.x * blockDim.x;

    // bias concat (first 768 quads' worth of threads handle 1 float4 each)
    if (i < 3 * D_MODEL / 4) {
        const float* src = (i < 256) ? bq : (i < 512) ? bk : bv;
        ((float4*)bqkv)[i] = ((const float4*)src)[i & 255];
    }

    for (; i < N4_TOT; i += stride) {
        const float* s;
        __half* d;
        int idx;
        if (i < N4_X) {
            s = x; d = xh; idx = i;
        } else if (i < N4_X + N4_POS) {
            s = pos; d = posh; idx = i - N4_X;
        } else {
            int wi = i - N4_X - N4_POS;
            int wsel = wi / N4_W;
            idx = wi - wsel * N4_W;
            s = (wsel == 0) ? Wq : (wsel == 1) ? Wk : (wsel == 2) ? Wv
                : (wsel == 3) ? Wo : Wp;
            d = wh + (size_t)wsel * (D_MODEL * D_MODEL);
        }
        float4 t = ((const float4*)s)[idx];
        uint2 r;
        r.x = pack_half2(t.x, t.y);
        r.y = pack_half2(t.z, t.w);
        ((uint2*)d)[idx] = r;
    }
}

// ============================ fp16 mma GEMM =================================
// Y[m,n] = sum_k X[m,k]*W[n,k] + bias[n]
// mode 0: fp32 out to Yv.
// mode 1: fused QKV: W is [3072,1024], bias is bqkv[3072]; out fp16 to
//         qkv[buf][m][n&1023] with buf = n>>10; buf 0 (q) adds P[m mod SEQ].
#define BM 128
#define BN 128
#define BKH 64                      /* k-halves per chunk (128 bytes) */
#define GSTAGES 4
#define NCHUNK (D_MODEL / BKH)      /* 16 */
#define TILE_B (BM * BKH * 2)       /* 16384 B */
#define STG_B  (2 * TILE_B)         /* 32768 B */
#define SM_TOTAL (GSTAGES * STG_B)  /* 131072 B */

__device__ __forceinline__ void gemm_load_chunk(
    const __half* __restrict__ X, const __half* __restrict__ W,
    uint32_t sbase, int stage, int m0, int n0, int kof, int tid)
{
    const uint32_t abase = sbase + stage * STG_B;
    const uint32_t bbase = abase + TILE_B;
#pragma unroll
    for (int i = 0; i < 2; i++) {
        int seg = tid + (i << 9);
        int row = seg >> 3, c16 = seg & 7;
        uint32_t off = row * 128 + c16 * 16;
        CP_ASYNC16(abase + SW128(off),
                   X + (size_t)(m0 + row) * D_MODEL + kof + c16 * 8);
    }
#pragma unroll
    for (int i = 0; i < 2; i++) {
        int seg = tid + (i << 9);
        int row = seg >> 3, c16 = seg & 7;
        uint32_t off = row * 128 + c16 * 16;
        CP_ASYNC16(bbase + SW128(off),
                   W + (size_t)(n0 + row) * D_MODEL + kof + c16 * 8);
    }
}

__global__ __launch_bounds__(512, 1) void gemm_f16_kernel(
    const __half* __restrict__ X, const __half* __restrict__ W,
    const float* __restrict__ bias, const float* __restrict__ P,
    void* __restrict__ Yv, int mode)
{
    extern __shared__ char smem[];
    const uint32_t sb = smem_u32(smem);
    const int tid = threadIdx.x;
    const int lane = tid & 31, wid = tid >> 5;
    const int wm = wid >> 2;          // 0..3
    const int wn = wid & 3;           // 0..3
    const int grp = lane >> 3, lrow = lane & 7;
    const int lq = lane >> 2, lr = lane & 3;
    const int n0 = blockIdx.x * BN;
    const int m0 = blockIdx.y * BM;

    float acc[2][4][4];
#pragma unroll
    for (int f = 0; f < 2; f++)
#pragma unroll
        for (int g = 0; g < 4; g++)
#pragma unroll
            for (int e = 0; e < 4; e++) acc[f][g][e] = 0.f;

#pragma unroll
    for (int c = 0; c < GSTAGES - 1; c++) {
        gemm_load_chunk(X, W, sb, c, m0, n0, c * BKH, tid);
        CP_COMMIT();
    }

    for (int m = 0; m < NCHUNK; m++) {
        CP_WAIT(GSTAGES - 2);
        __syncthreads();

        const int pc = m + GSTAGES - 1;
        if (pc < NCHUNK)
            gemm_load_chunk(X, W, sb, pc & (GSTAGES - 1), m0, n0, pc * BKH, tid);
        CP_COMMIT();

        const uint32_t abase = sb + (m & (GSTAGES - 1)) * STG_B;
        const uint32_t bbase = abase + TILE_B;
#pragma unroll
        for (int ks = 0; ks < 4; ks++) {
            const int kc = ks * 16;
            uint32_t A[2][4], B[2][4];
#pragma unroll
            for (int f = 0; f < 2; f++) {
                const int r = wm * 32 + f * 16 + lrow + (grp & 1) * 8;
                const int c = kc + (grp >> 1) * 8;
                LDSM4(A[f][0], A[f][1], A[f][2], A[f][3],
                      abase + SW128((uint32_t)(r * 128 + c * 2)));
            }
#pragma unroll
            for (int u = 0; u < 2; u++) {
                const int r = wn * 32 + u * 16 + lrow + (grp >> 1) * 8;
                const int c = kc + (grp & 1) * 8;
                LDSM4(B[u][0], B[u][1], B[u][2], B[u][3],
                      bbase + SW128((uint32_t)(r * 128 + c * 2)));
            }
#pragma unroll
            for (int f = 0; f < 2; f++)
#pragma unroll
                for (int u = 0; u < 2; u++) {
                    MMA_F16(acc[f][2 * u],     A[f][0], A[f][1], A[f][2], A[f][3],
                            B[u][0], B[u][1]);
                    MMA_F16(acc[f][2 * u + 1], A[f][0], A[f][1], A[f][2], A[f][3],
                            B[u][2], B[u][3]);
                }
        }
    }

    if (mode == 1) {
        // fused QKV epilogue: n0 block lies wholly inside one of q/k/v
        const int buf = n0 >> 10;
        __half* Yh = (__half*)Yv + (size_t)buf * (NTOK * D_MODEL);
        const int addP = (buf == 0);
#pragma unroll
        for (int f = 0; f < 2; f++) {
            const int r0 = m0 + wm * 32 + f * 16 + lq;
#pragma unroll
            for (int g = 0; g < 4; g++) {
                const int nc = n0 + wn * 32 + g * 8 + 2 * lr;
                const int col = nc & 1023;
                float2 bz = *(const float2*)(bias + nc);
                float2 v0, v1;
                v0.x = acc[f][g][0] + bz.x; v0.y = acc[f][g][1] + bz.y;
                v1.x = acc[f][g][2] + bz.x; v1.y = acc[f][g][3] + bz.y;
                if (addP) {
                    float2 p0 = *(const float2*)(P + (size_t)(r0 & (SEQ - 1)) * D_MODEL + col);
                    float2 p1 = *(const float2*)(P + (size_t)((r0 + 8) & (SEQ - 1)) * D_MODEL + col);
                    v0.x += p0.x; v0.y += p0.y;
                    v1.x += p1.x; v1.y += p1.y;
                }
                *(uint32_t*)(Yh + (size_t)r0 * D_MODEL + col) = pack_half2(v0.x, v0.y);
                *(uint32_t*)(Yh + (size_t)(r0 + 8) * D_MODEL + col) = pack_half2(v1.x, v1.y);
            }
        }
    } else {
        float* Yf = (float*)Yv;
#pragma unroll
        for (int f = 0; f < 2; f++) {
            const int r0 = m0 + wm * 32 + f * 16 + lq;
#pragma unroll
            for (int g = 0; g < 4; g++) {
                const int nc = n0 + wn * 32 + g * 8 + 2 * lr;
                float2 bz = *(const float2*)(bias + nc);
                float2 v0, v1;
                v0.x = acc[f][g][0] + bz.x; v0.y = acc[f][g][1] + bz.y;
                v1.x = acc[f][g][2] + bz.x; v1.y = acc[f][g][3] + bz.y;
                *(float2*)(Yf + (size_t)r0 * D_MODEL + nc) = v0;
                *(float2*)(Yf + (size_t)(r0 + 8) * D_MODEL + nc) = v1;
            }
        }
    }
}

// ============================ fp16 flash attention ==========================
// BQ=128 (8 warps x m16), BJ=64, dk=64. Q frags in regs; K/V double-buffered
// cp.async, SW128 rows, ldmatrix (V via .trans). P stays in registers.
#define BQ 128
#define BJ 64
#define KTILE_B (BJ * 64 * 2)            /* 8192 B per stage */
#define AVB_OFF (2 * KTILE_B)            /* V after 2 K stages */
#define ATT_SMEM (4 * KTILE_B)           /* 32768 B */

__global__ __launch_bounds__(256, 1) void flash_f16_kernel(
    const __half* __restrict__ Q, const __half* __restrict__ K,
    const __half* __restrict__ V, __half* __restrict__ O)
{
    extern __shared__ char smem[];
    const uint32_t sb = smem_u32(smem);
    const int tid = threadIdx.x;
    const int lane = tid & 31, w = tid >> 5;
    const int lq = lane >> 2, lr = lane & 3;
    const int grp = lane >> 3, lrow = lane & 7;
    const int qt = gridDim.x - 1 - blockIdx.x;   // heavy tiles first
    const int bh = blockIdx.y;
    const int b = bh >> 4, h = bh & 15;
    const int q0 = qt * BQ;
    const size_t base = ((size_t)b * SEQ) * D_MODEL + h * 64;

    uint32_t qa[4][4];
    {
        const __half* q0p = Q + base + (size_t)(q0 + w * 16 + lq) * D_MODEL;
        const __half* q1p = q0p + 8 * D_MODEL;
#pragma unroll
        for (int ks = 0; ks < 4; ks++) {
            const int c = ks * 16 + 2 * lr;
            qa[ks][0] = *(const uint32_t*)(q0p + c);
            qa[ks][1] = *(const uint32_t*)(q1p + c);
            qa[ks][2] = *(const uint32_t*)(q0p + c + 8);
            qa[ks][3] = *(const uint32_t*)(q1p + c + 8);
        }
    }

    float o[8][4];
#pragma unroll
    for (int g = 0; g < 8; g++)
#pragma unroll
        for (int e = 0; e < 4; e++) o[g][e] = 0.f;
    float m0 = -1e30f, m1 = -1e30f, l0 = 0.f, l1 = 0.f;

    const int nj = qt * 2 + 2;

#define LOAD_KV(t_) do {                                                      \
    const int s_ = (t_) & 1;                                                  \
    const __half* kg = K + base + (size_t)((t_) * BJ) * D_MODEL;              \
    const __half* vg = V + base + (size_t)((t_) * BJ) * D_MODEL;              \
    const uint32_t kb = sb + s_ * KTILE_B;                                    \
    const uint32_t vb = sb + AVB_OFF + s_ * KTILE_B;                          \
    _Pragma("unroll")                                                         \
    for (int i_ = 0; i_ < 4; i_++) {                                          \
        int seg = tid + (i_ << 8);          /* 0..1023 */                     \
        int kv = seg >> 9;                  /* 0=K, 1=V */                    \
        int s2 = seg & 511;                                                   \
        int row = s2 >> 3, c16 = s2 & 7;                                      \
        uint32_t off = SW128((uint32_t)(row * 128 + c16 * 16));               \
        const __half* src = (kv ? vg : kg) + (size_t)row * D_MODEL + c16 * 8; \
        CP_ASYNC16((kv ? vb : kb) + off, src);                                \
    }                                                                         \
} while (0)

    LOAD_KV(0);
    CP_COMMIT();

    const int qw = q0 + w * 16;
    const int qmax = qw + 15;

    for (int t = 0; t < nj; t++) {
        CP_WAIT(0);
        __syncthreads();
        if (t + 1 < nj) { LOAD_KV(t + 1); CP_COMMIT(); }

        const uint32_t kbase = sb + (t & 1) * KTILE_B;
        const uint32_t vbase = sb + AVB_OFF + (t & 1) * KTILE_B;
        const int j0 = t * BJ;

        float s[8][4];
#pragma unroll
        for (int g = 0; g < 8; g++) {
            float init = ((j0 + g * 8) <= qmax) ? 0.f : -1e30f;
            s[g][0] = init; s[g][1] = init; s[g][2] = init; s[g][3] = init;
        }
#pragma unroll
        for (int ks = 0; ks < 4; ks++) {
            const int kc = ks * 16;
#pragma unroll
            for (int u = 0; u < 4; u++) {
                if ((j0 + u * 16) > qmax) continue;
                const int r = u * 16 + lrow + (grp >> 1) * 8;
                const int c = kc + (grp & 1) * 8;
                uint32_t b0, b1, b2, b3;
                LDSM4(b0, b1, b2, b3, kbase + SW128((uint32_t)(r * 128 + c * 2)));
                MMA_F16(s[2 * u],     qa[ks][0], qa[ks][1], qa[ks][2], qa[ks][3], b0, b1);
                MMA_F16(s[2 * u + 1], qa[ks][0], qa[ks][1], qa[ks][2], qa[ks][3], b2, b3);
            }
        }

#pragma unroll
        for (int g = 0; g < 8; g++) {
            s[g][0] *= 0.125f; s[g][1] *= 0.125f;
            s[g][2] *= 0.125f; s[g][3] *= 0.125f;
        }
        if (j0 + BJ - 1 > qw) {
            const int Q0 = qw + lq, Q1 = Q0 + 8;
#pragma unroll
            for (int g = 0; g < 8; g++) {
                const int jc = j0 + g * 8 + 2 * lr;
                if (jc     > Q0) s[g][0] = -1e30f;
                if (jc + 1 > Q0) s[g][1] = -1e30f;
                if (jc     > Q1) s[g][2] = -1e30f;
                if (jc + 1 > Q1) s[g][3] = -1e30f;
            }
        }

        float mx0 = -1e30f, mx1 = -1e30f;
#pragma unroll
        for (int g = 0; g < 8; g++) {
            mx0 = fmaxf(mx0, fmaxf(s[g][0], s[g][1]));
            mx1 = fmaxf(mx1, fmaxf(s[g][2], s[g][3]));
        }
        mx0 = fmaxf(mx0, __shfl_xor_sync(0xffffffffu, mx0, 1));
        mx0 = fmaxf(mx0, __shfl_xor_sync(0xffffffffu, mx0, 2));
        mx1 = fmaxf(mx1, __shfl_xor_sync(0xffffffffu, mx1, 1));
        mx1 = fmaxf(mx1, __shfl_xor_sync(0xffffffffu, mx1, 2));
        const float mn0 = fmaxf(m0, mx0), mn1 = fmaxf(m1, mx1);
        const float c0 = __expf(m0 - mn0), c1 = __expf(m1 - mn1);
        m0 = mn0; m1 = mn1;
        float sum0 = 0.f, sum1 = 0.f;
#pragma unroll
        for (int g = 0; g < 8; g++) {
            s[g][0] = __expf(s[g][0] - mn0);
            s[g][1] = __expf(s[g][1] - mn0);
            s[g][2] = __expf(s[g][2] - mn1);
            s[g][3] = __expf(s[g][3] - mn1);
            sum0 += s[g][0] + s[g][1];
            sum1 += s[g][2] + s[g][3];
        }
        sum0 += __shfl_xor_sync(0xffffffffu, sum0, 1);
        sum0 += __shfl_xor_sync(0xffffffffu, sum0, 2);
        sum1 += __shfl_xor_sync(0xffffffffu, sum1, 1);
        sum1 += __shfl_xor_sync(0xffffffffu, sum1, 2);
        l0 = l0 * c0 + sum0;
        l1 = l1 * c1 + sum1;
#pragma unroll
        for (int g = 0; g < 8; g++) {
            o[g][0] *= c0; o[g][1] *= c0;
            o[g][2] *= c1; o[g][3] *= c1;
        }

        uint32_t pa[4][4];
#pragma unroll
        for (int u = 0; u < 4; u++) {
            pa[u][0] = pack_half2(s[2 * u][0],     s[2 * u][1]);
            pa[u][1] = pack_half2(s[2 * u][2],     s[2 * u][3]);
            pa[u][2] = pack_half2(s[2 * u + 1][0], s[2 * u + 1][1]);
            pa[u][3] = pack_half2(s[2 * u + 1][2], s[2 * u + 1][3]);
        }

#pragma unroll
        for (int kj = 0; kj < 4; kj++) {
            const int jb = kj * 16;
#pragma unroll
            for (int u = 0; u < 4; u++) {
                const int r = jb + lrow + (grp & 1) * 8;
                const int c = u * 16 + (grp >> 1) * 8;
                uint32_t b0, b1, b2, b3;
                LDSM4T(b0, b1, b2, b3, vbase + SW128((uint32_t)(r * 128 + c * 2)));
                MMA_F16(o[2 * u],     pa[kj][0], pa[kj][1], pa[kj][2], pa[kj][3], b0, b1);
                MMA_F16(o[2 * u + 1], pa[kj][0], pa[kj][1], pa[kj][2], pa[kj][3], b2, b3);
            }
        }
    }

    const float inv0 = 1.f / l0, inv1 = 1.f / l1;
    __half* o0 = O + base + (size_t)(qw + lq) * D_MODEL;
    __half* o1 = o0 + 8 * D_MODEL;
#pragma unroll
    for (int g = 0; g < 8; g++) {
        const int c = g * 8 + 2 * lr;
        *(uint32_t*)(o0 + c) = pack_half2(o[g][0] * inv0, o[g][1] * inv0);
        *(uint32_t*)(o1 + c) = pack_half2(o[g][2] * inv1, o[g][3] * inv1);
    }
}

// ---------------------------------------------------------------------------
extern "C" void kernel_launch(void* const* d_in, const int* in_sizes, int n_in,
                              void* d_out, int out_size)
{
    const float* x   = (const float*)d_in[0];
    const float* pos = (const float*)d_in[1];
    const float* Wq  = (const float*)d_in[2];
    const float* bq  = (const float*)d_in[3];
    const float* Wk  = (const float*)d_in[4];
    const float* bk  = (const float*)d_in[5];
    const float* Wv  = (const float*)d_in[6];
    const float* bv  = (const float*)d_in[7];
    const float* Wp  = (const float*)d_in[8];
    const float* bp  = (const float*)d_in[9];
    const float* Wo  = (const float*)d_in[10];
    const float* bo  = (const float*)d_in[11];
    float* out = (float*)d_out;

    __half *xh, *posh, *wh, *qkvh, *ctxh;
    float *p, *bqkv;
    cudaGetSymbolAddress((void**)&xh,   g_xh);
    cudaGetSymbolAddress((void**)&posh, g_posh);
    cudaGetSymbolAddress((void**)&wh,   g_wh);
    cudaGetSymbolAddress((void**)&qkvh, g_qkvh);
    cudaGetSymbolAddress((void**)&ctxh, g_ctxh);
    cudaGetSymbolAddress((void**)&p,    g_p);
    cudaGetSymbolAddress((void**)&bqkv, g_bqkv);

    __half* wqkvh = wh;                                  // [3072, 1024]
    __half* woh   = wh + 3 * (size_t)D_MODEL * D_MODEL;
    __half* wph   = wh + 4 * (size_t)D_MODEL * D_MODEL;
    __half* qh = qkvh;
    __half* kh = qkvh + 1 * (size_t)NTOK * D_MODEL;
    __half* vh = qkvh + 2 * (size_t)NTOK * D_MODEL;

    static bool attr_done = false;
    if (!attr_done) {
        cudaFuncSetAttribute(gemm_f16_kernel,
                             cudaFuncAttributeMaxDynamicSharedMemorySize, SM_TOTAL);
        cudaFuncSetAttribute(flash_f16_kernel,
                             cudaFuncAttributeMaxDynamicSharedMemorySize, ATT_SMEM);
        attr_done = true;
    }

    // one fused pack (x, pos, 5 weights, bias concat)
    pack_all_kernel<<<2960, 256>>>(x, pos, Wq, Wk, Wv, Wo, Wp, bq, bk, bv,
                                   xh, posh, wh, bqkv);

    dim3 blk(512);
    // p = pos @ Wp^T + bp (fp32)
    gemm_f16_kernel<<<dim3(8, 16), blk, SM_TOTAL>>>(posh, wph, bp, nullptr, p, 0);
    // fused QKV: [8192, 3072]
    gemm_f16_kernel<<<dim3(24, 64), blk, SM_TOTAL>>>(xh, wqkvh, bqkv, p, qkvh, 1);
    // attention -> ctx (fp16)
    flash_f16_kernel<<<dim3(SEQ / BQ, BATCH * 16), 256, ATT_SMEM>>>(qh, kh, vh, ctxh);
    // out = ctx @ Wo^T + bo (fp32)
    gemm_f16_kernel<<<dim3(8, 64), blk, SM_TOTAL>>>(ctxh, woh, bo, nullptr, out, 0);
}